// round 3
// baseline (speedup 1.0000x reference)
#include <cuda_runtime.h>

#define NP  66
#define NPP 72

// ---------------- scratch (no allocations allowed) ----------------
__device__ __align__(16) float g_O0[8 * NP * 32 * 32];
__device__ __align__(16) float g_O1[8 * NP * 64 * 64];
__device__ __align__(16) float g_O2[8 * NP * 128 * 128];

__constant__ int c_I[NP] = {
  0,0,0,0,0,0,0,0,0,0,0,
  1,1,1,1,1,1,1,1,1,1,
  2,2,2,2,2,2,2,2,2,
  3,3,3,3,3,3,3,3,
  4,4,4,4,4,4,4,
  5,5,5,5,5,5,
  6,6,6,6,6,
  7,7,7,7,
  8,8,8,
  9,9,
  10};
__constant__ int c_J[NP] = {
  1,2,3,4,5,6,7,8,9,10,11,
  2,3,4,5,6,7,8,9,10,11,
  3,4,5,6,7,8,9,10,11,
  4,5,6,7,8,9,10,11,
  5,6,7,8,9,10,11,
  6,7,8,9,10,11,
  7,8,9,10,11,
  8,9,10,11,
  9,10,11,
  10,11,
  11};

// ---------------- f32x2 packed-math helpers ----------------
__device__ __forceinline__ void ffma2(unsigned long long& d,
                                      unsigned long long a,
                                      unsigned long long b) {
  asm("fma.rn.f32x2 %0, %1, %2, %0;" : "+l"(d) : "l"(a), "l"(b));
}
__device__ __forceinline__ unsigned long long pack2(float x) {
  unsigned long long r;
  asm("mov.b64 %0, {%1, %1};" : "=l"(r) : "f"(x));
  return r;
}
__device__ __forceinline__ float2 unpack2(unsigned long long u) {
  float2 r;
  asm("mov.b64 {%0, %1}, %2;" : "=f"(r.x), "=f"(r.y) : "l"(u));
  return r;
}

// XOR swizzle on 16-byte-unit index (kills 2-way conflict of stride-32B LDS.128)
#define XSW(u) ((u) ^ (((u) >> 3) & 1))

// ---------------- shared conv body: 68 pairs x 128 px, FFMA2 ----------------
// block = 288 threads: pi=tid>>4 (pair group of 4), pj=tid&15 (8 px each)
template <int C, int SS>
__device__ __forceinline__ void conv_body(const float* __restrict__ X,
                                          const float* __restrict__ W,
                                          const float* __restrict__ bias,
                                          float* __restrict__ Og,
                                          int n, int px0,
                                          float* Ws2, float* Xs) {
  const int tid = threadIdx.x;
  const int pi = tid >> 4, pj = tid & 15;

  unsigned long long acc[4][4];
#pragma unroll
  for (int a = 0; a < 4; a++) {
    int p = 4 * pi + a;
    unsigned long long pk = pack2((p < NP) ? bias[p] : 0.0f);
#pragma unroll
    for (int h = 0; h < 4; h++) acc[a][h] = pk;
  }

  const float* Xn = X + (size_t)n * C * SS + px0;

  for (int c0 = 0; c0 < C; c0 += 16) {
    __syncthreads();
#pragma unroll
    for (int r = 0; r < 4; r++) {
      int f = tid + r * 288;
      int k = f / NPP, p = f - k * NPP;
      float wv = (p < NP) ? W[p * C + c0 + k] : 0.0f;  // on-the-fly transpose
      *(float2*)&Ws2[k * 144 + 2 * p] = make_float2(wv, wv);
    }
#pragma unroll
    for (int t = 0; t < 2; t++) {
      int f = tid + t * 288;
      if (f < 512) {
        int c = f >> 5, q = f & 31;
        *(float4*)&Xs[c * 128 + 4 * XSW(q)] =
            *(const float4*)&Xn[(size_t)(c0 + c) * SS + 4 * q];
      }
    }
    __syncthreads();
#pragma unroll
    for (int k = 0; k < 16; k++) {
      const ulonglong2 wA = *(const ulonglong2*)&Ws2[k * 144 + 8 * pi];
      const ulonglong2 wB = *(const ulonglong2*)&Ws2[k * 144 + 8 * pi + 4];
      const ulonglong2 xA = *(const ulonglong2*)&Xs[k * 128 + 4 * XSW(2 * pj)];
      const ulonglong2 xB = *(const ulonglong2*)&Xs[k * 128 + 4 * XSW(2 * pj + 1)];
      unsigned long long w_[4] = {wA.x, wA.y, wB.x, wB.y};
      unsigned long long x_[4] = {xA.x, xA.y, xB.x, xB.y};
#pragma unroll
      for (int a = 0; a < 4; a++)
#pragma unroll
        for (int h = 0; h < 4; h++) ffma2(acc[a][h], w_[a], x_[h]);
    }
  }

  float* On = Og + (size_t)n * NP * SS + px0 + 8 * pj;
#pragma unroll
  for (int a = 0; a < 4; a++) {
    int p = 4 * pi + a;
    if (p < NP) {
      ulonglong2 v0, v1;
      v0.x = acc[a][0]; v0.y = acc[a][1];
      v1.x = acc[a][2]; v1.y = acc[a][3];
      *(ulonglong2*)&On[(size_t)p * SS] = v0;
      *(ulonglong2*)&On[(size_t)p * SS + 4] = v1;
    }
  }
}

// ---------------- merged conv for stages 0..2 ----------------
__global__ __launch_bounds__(288, 2) void conv_all(
    const float* __restrict__ s0, const float* __restrict__ s1,
    const float* __restrict__ s2, const float* __restrict__ w0,
    const float* __restrict__ w1, const float* __restrict__ w2,
    const float* __restrict__ b0, const float* __restrict__ b1,
    const float* __restrict__ b2) {
  __shared__ __align__(16) float Ws2[16 * 144];
  __shared__ __align__(16) float Xs[16 * 128];
  int bid = blockIdx.x;
  if (bid < 64) {
    conv_body<512, 32 * 32>(s0, w0, b0, g_O0, bid >> 3, (bid & 7) << 7, Ws2, Xs);
  } else if (bid < 320) {
    int q = bid - 64;
    conv_body<256, 64 * 64>(s1, w1, b1, g_O1, q >> 5, (q & 31) << 7, Ws2, Xs);
  } else {
    int q = bid - 320;
    conv_body<128, 128 * 128>(s2, w2, b2, g_O2, q >> 7, (q & 127) << 7, Ws2, Xs);
  }
}

// bilinear constant tables (half-pixel, y0/x0 multiples of 8 -> static)
// factor 8: rel = {0,0,0,0,1,1,1,1}, frac = (r<4 ? (r+4.5)/8 : (r-3.5)/8)
// factor 4: rel = {0,0,1,1,1,1,2,2}, frac = {.625,.875,.125,.375}x2
// factor 2: rel = {0,1,1,2,2,3,3,4}, frac = {.75,.25}x4

// ---------------- fused: stage3 conv + bilinear pyramid sum + popc vote ----------------
// tile = 8 rows x 16 cols, flat px = row*16+col; thread pj owns px 8pj..8pj+7
__global__ __launch_bounds__(288, 2) void fused_kernel(
    const float* __restrict__ X, const float* __restrict__ W,
    const float* __restrict__ bias, float* __restrict__ out) {
  __shared__ __align__(16) float Ws2[16 * 144];
  __shared__ __align__(16) float Xs[16 * 128];
  __shared__ __align__(16) float sO2[NP * 72];   // 6 rows x 10 cols (pad 12)
  __shared__ __align__(16) float sO1[NP * 32];   // 4 x 6 (pad 8)
  __shared__ __align__(16) float sO0[NP * 12];   // 3 x 4
  __shared__ unsigned sSigns[17 * 32];           // [pi][128 px] nibble bytes
  __shared__ __align__(16) int sMask[12][8];

  const int tid = threadIdx.x;
  const int pi = tid >> 4, pj = tid & 15;
  const int n = blockIdx.y;
  const int ty = blockIdx.x >> 4, tx = blockIdx.x & 15;
  const int y0 = ty << 3, x0 = tx << 4;

  // vote masks (static function of c_I/c_J); one warp, before first sync
  if (tid >= 96 && tid < 108) {
    int k = tid - 96;
    int m[6] = {0, 0, 0, 0, 0, 0};
    for (int p = 0; p < NP; p++) {
      int word = p >> 5, bit = p & 31;
      if (c_I[p] == k) m[word] |= 1 << bit;
      if (c_J[p] == k) m[3 + word] |= 1 << bit;
    }
#pragma unroll
    for (int t = 0; t < 6; t++) sMask[k][t] = m[t];
    sMask[k][6] = k; sMask[k][7] = 0;
  }

  {  // stage O2 region (128x128 src): 6 rows x 10 cols per pair, pad 12
    const float* src = g_O2 + (size_t)n * NP * 16384;
    int by = (y0 >> 1) - 1, bx = (x0 >> 1) - 1;
    for (int i = tid; i < NP * 60; i += 288) {
      int p = i / 60, cell = i - p * 60;
      int rr = cell / 10, cc = cell - rr * 10;
      int sy = min(max(by + rr, 0), 127);
      int sx = min(max(bx + cc, 0), 127);
      sO2[p * 72 + rr * 12 + cc] = src[p * 16384 + sy * 128 + sx];
    }
  }
  {  // stage O1 region (64x64 src): 4 x 6, pad 8
    const float* src = g_O1 + (size_t)n * NP * 4096;
    int by = (y0 >> 2) - 1, bx = (x0 >> 2) - 1;
    for (int i = tid; i < NP * 24; i += 288) {
      int p = i / 24, cell = i - p * 24;
      int rr = cell / 6, cc = cell - rr * 6;
      int sy = min(max(by + rr, 0), 63);
      int sx = min(max(bx + cc, 0), 63);
      sO1[p * 32 + rr * 8 + cc] = src[p * 4096 + sy * 64 + sx];
    }
  }
  {  // stage O0 region (32x32 src): 3 x 4
    const float* src = g_O0 + (size_t)n * NP * 1024;
    int by = (y0 >> 3) - 1, bx = (x0 >> 3) - 1;
    for (int i = tid; i < NP * 12; i += 288) {
      int p = i / 12, cell = i - p * 12;
      int rr = cell >> 2, cc = cell & 3;
      int sy = min(max(by + rr, 0), 31);
      int sx = min(max(bx + cc, 0), 31);
      sO0[p * 12 + rr * 4 + cc] = src[p * 1024 + sy * 32 + sx];
    }
  }

  // ---- stage3 GEMM mainloop (C=64) ----
  unsigned long long acc[4][4];
#pragma unroll
  for (int a = 0; a < 4; a++) {
    int p = 4 * pi + a;
    unsigned long long pk = pack2((p < NP) ? bias[p] : 0.0f);
#pragma unroll
    for (int h = 0; h < 4; h++) acc[a][h] = pk;
  }
  const float* Xn = X + (size_t)n * 64 * 65536;

  for (int c0 = 0; c0 < 64; c0 += 16) {
    __syncthreads();
#pragma unroll
    for (int r = 0; r < 4; r++) {
      int f = tid + r * 288;
      int k = f / NPP, p = f - k * NPP;
      float wv = (p < NP) ? W[p * 64 + c0 + k] : 0.0f;
      *(float2*)&Ws2[k * 144 + 2 * p] = make_float2(wv, wv);
    }
#pragma unroll
    for (int t = 0; t < 2; t++) {
      int f = tid + t * 288;
      if (f < 512) {
        int c = f >> 5, q = f & 31;
        int rr = q >> 2, c4 = (q & 3) << 2;
        *(float4*)&Xs[c * 128 + 4 * XSW(q)] =
            *(const float4*)&Xn[((size_t)(c0 + c) * 256 + (y0 + rr)) * 256 + x0 + c4];
      }
    }
    __syncthreads();
#pragma unroll
    for (int k = 0; k < 16; k++) {
      const ulonglong2 wA = *(const ulonglong2*)&Ws2[k * 144 + 8 * pi];
      const ulonglong2 wB = *(const ulonglong2*)&Ws2[k * 144 + 8 * pi + 4];
      const ulonglong2 xA = *(const ulonglong2*)&Xs[k * 128 + 4 * XSW(2 * pj)];
      const ulonglong2 xB = *(const ulonglong2*)&Xs[k * 128 + 4 * XSW(2 * pj + 1)];
      unsigned long long w_[4] = {wA.x, wA.y, wB.x, wB.y};
      unsigned long long x_[4] = {xA.x, xA.y, xB.x, xB.y};
#pragma unroll
      for (int a = 0; a < 4; a++)
#pragma unroll
        for (int h = 0; h < 4; h++) ffma2(acc[a][h], w_[a], x_[h]);
    }
  }

  // ---- epilogue: separable bilinear (octet-shared taps) + sign nibbles ----
  {
    const int r = pj >> 1;          // output row in tile (0..7)
    const int oxb = (pj & 1) << 3;  // column octet base (0 or 8)
    // y constants
    const float WY2[8] = {.75f, .25f, .75f, .25f, .75f, .25f, .75f, .25f};
    const int   RY2[8] = {0, 1, 1, 2, 2, 3, 3, 4};
    const float WY1[8] = {.625f, .875f, .125f, .375f, .625f, .875f, .125f, .375f};
    const int   RY1[8] = {0, 0, 1, 1, 1, 1, 2, 2};
    const float WY0[8] = {.5625f, .6875f, .8125f, .9375f, .0625f, .1875f, .3125f, .4375f};
    const int   RY0[8] = {0, 0, 0, 0, 1, 1, 1, 1};
    // x constants (q within octet)
    const float WX2[8] = {.75f, .25f, .75f, .25f, .75f, .25f, .75f, .25f};
    const int   OX2[8] = {0, 1, 1, 2, 2, 3, 3, 4};
    const float WX1[8] = {.625f, .875f, .125f, .375f, .625f, .875f, .125f, .375f};
    const int   OX1[8] = {0, 0, 1, 1, 1, 1, 2, 2};
    const float WX0[8] = {.5625f, .6875f, .8125f, .9375f, .0625f, .1875f, .3125f, .4375f};
    const int   OX0[8] = {0, 0, 0, 0, 1, 1, 1, 1};

    const int ry2 = RY2[r]; const float wy2 = WY2[r];
    const int ry1 = RY1[r]; const float wy1 = WY1[r];
    const int ry0 = RY0[r]; const float wy0 = WY0[r];
    const int b2 = oxb >> 1, b1 = oxb >> 2, b0 = oxb >> 3;

    unsigned nibLo = 0, nibHi = 0;
    if (pi < 17) {
#pragma unroll
      for (int a = 0; a < 4; a++) {
        int p = 4 * pi + a;
        float v[8];
#pragma unroll
        for (int h = 0; h < 4; h++) {
          float2 t = unpack2(acc[a][h]);
          v[2 * h] = t.x; v[2 * h + 1] = t.y;
        }
        if (p < NP) {
          // L2: y-lerp 6 consecutive taps (vector loads)
          float ty2[6];
          {
            const float* rA = &sO2[p * 72 + ry2 * 12 + b2];
            const float* rB = rA + 12;
            float4 a4 = *(const float4*)rA;  float2 a2 = *(const float2*)(rA + 4);
            float4 b4 = *(const float4*)rB;  float2 b2v = *(const float2*)(rB + 4);
            ty2[0] = a4.x + wy2 * (b4.x - a4.x);
            ty2[1] = a4.y + wy2 * (b4.y - a4.y);
            ty2[2] = a4.z + wy2 * (b4.z - a4.z);
            ty2[3] = a4.w + wy2 * (b4.w - a4.w);
            ty2[4] = a2.x + wy2 * (b2v.x - a2.x);
            ty2[5] = a2.y + wy2 * (b2v.y - a2.y);
          }
          // L1: 4 taps
          float ty1[4];
          {
            const float* rA = &sO1[p * 32 + ry1 * 8 + b1];
            const float* rB = rA + 8;
            float2 a0 = *(const float2*)rA, a1 = *(const float2*)(rA + 2);
            float2 c0v = *(const float2*)rB, c1 = *(const float2*)(rB + 2);
            ty1[0] = a0.x + wy1 * (c0v.x - a0.x);
            ty1[1] = a0.y + wy1 * (c0v.y - a0.y);
            ty1[2] = a1.x + wy1 * (c1.x - a1.x);
            ty1[3] = a1.y + wy1 * (c1.y - a1.y);
          }
          // L0: 3 taps (row float4 + select by b0)
          float ty0[3];
          {
            const float* rA = &sO0[p * 12 + (ry0 << 2)];
            float4 a4 = *(const float4*)rA;
            float4 b4 = *(const float4*)(rA + 4);
            float a0 = b0 ? a4.y : a4.x, a1 = b0 ? a4.z : a4.y, a2 = b0 ? a4.w : a4.z;
            float c0v = b0 ? b4.y : b4.x, c1 = b0 ? b4.z : b4.y, c2 = b0 ? b4.w : b4.z;
            ty0[0] = a0 + wy0 * (c0v - a0);
            ty0[1] = a1 + wy0 * (c1 - a1);
            ty0[2] = a2 + wy0 * (c2 - a2);
          }
#pragma unroll
          for (int q = 0; q < 8; q++) {
            float lo2 = ty2[OX2[q]], hi2 = ty2[OX2[q] + 1];
            float lo1 = ty1[OX1[q]], hi1 = ty1[OX1[q] + 1];
            float lo0 = ty0[OX0[q]], hi0 = ty0[OX0[q] + 1];
            v[q] += lo2 + WX2[q] * (hi2 - lo2);
            v[q] += lo1 + WX1[q] * (hi1 - lo1);
            v[q] += lo0 + WX0[q] * (hi0 - lo0);
          }
        }
#pragma unroll
        for (int q = 0; q < 8; q++) {
          unsigned bit = (v[q] > 0.0f) ? 1u : 0u;
          if (q < 4) nibLo |= bit << ((q << 3) + a);
          else       nibHi |= bit << (((q - 4) << 3) + a);
        }
      }
      sSigns[pi * 32 + 2 * pj]     = nibLo;
      sSigns[pi * 32 + 2 * pj + 1] = nibHi;
    }
  }
  __syncthreads();

  // ---- vote via popcount masks, direct coalesced store ----
  if (tid < 128) {
    const unsigned char* sb = (const unsigned char*)sSigns;
    unsigned sw0 = 0, sw1 = 0;
#pragma unroll
    for (int g = 0; g < 8; g++) sw0 |= (unsigned)sb[g * 128 + tid] << (4 * g);
#pragma unroll
    for (int g = 8; g < 16; g++) sw1 |= (unsigned)sb[g * 128 + tid] << (4 * (g - 8));
    unsigned sw2 = sb[16 * 128 + tid];
    int row = tid >> 4, col = tid & 15;
    float* op = out + (size_t)n * 12 * 65536 + (y0 + row) * 256 + (x0 + col);
#pragma unroll
    for (int k = 0; k < 12; k++) {
      int4 A = *(const int4*)&sMask[k][0];
      int4 B = *(const int4*)&sMask[k][4];
      int cnt = __popc(sw0 & (unsigned)A.x) + __popc(sw1 & (unsigned)A.y) +
                __popc(sw2 & (unsigned)A.z) - __popc(sw0 & (unsigned)A.w) -
                __popc(sw1 & (unsigned)B.x) - __popc(sw2 & (unsigned)B.y) + k;
      op[(size_t)k << 16] = (float)cnt;
    }
  }
}

// ---------------- launcher ----------------
extern "C" void kernel_launch(void* const* d_in, const int* in_sizes, int n_in,
                              void* d_out, int out_size) {
  const float* st[4] = {0, 0, 0, 0};
  const float* w[4] = {0, 0, 0, 0};
  const float* bb[4] = {0, 0, 0, 0};
  int bc = 0;
  for (int i = 0; i < n_in; i++) {
    switch (in_sizes[i]) {
      case 4194304:  st[0] = (const float*)d_in[i]; break;  // 8*512*32*32
      case 8388608:  st[1] = (const float*)d_in[i]; break;  // 8*256*64*64
      case 16777216: st[2] = (const float*)d_in[i]; break;  // 8*128*128*128
      case 33554432: st[3] = (const float*)d_in[i]; break;  // 8*64*256*256
      case 33792: w[0] = (const float*)d_in[i]; break;      // 66*512
      case 16896: w[1] = (const float*)d_in[i]; break;      // 66*256
      case 8448:  w[2] = (const float*)d_in[i]; break;      // 66*128
      case 4224:  w[3] = (const float*)d_in[i]; break;      // 66*64
      case 66:
        if (bc < 4) bb[bc++] = (const float*)d_in[i];       // b0..b3 in order
        break;
      default: break;  // last_only (==1 always per setup_inputs)
    }
  }

  conv_all<<<1344, 288>>>(st[0], st[1], st[2], w[0], w[1], w[2],
                          bb[0], bb[1], bb[2]);
  fused_kernel<<<dim3(512, 8), 288>>>(st[3], w[3], bb[3], (float*)d_out);
}

// round 4
// speedup vs baseline: 1.0794x; 1.0794x over previous
#include <cuda_runtime.h>

#define NP  66
#define NPP 72

// ---------------- scratch (no allocations allowed) ----------------
__device__ __align__(16) float g_O0[8 * NP * 32 * 32];
__device__ __align__(16) float g_O1[8 * NP * 64 * 64];
__device__ __align__(16) float g_O2[8 * NP * 128 * 128];

__constant__ int c_I[NP] = {
  0,0,0,0,0,0,0,0,0,0,0,
  1,1,1,1,1,1,1,1,1,1,
  2,2,2,2,2,2,2,2,2,
  3,3,3,3,3,3,3,3,
  4,4,4,4,4,4,4,
  5,5,5,5,5,5,
  6,6,6,6,6,
  7,7,7,7,
  8,8,8,
  9,9,
  10};
__constant__ int c_J[NP] = {
  1,2,3,4,5,6,7,8,9,10,11,
  2,3,4,5,6,7,8,9,10,11,
  3,4,5,6,7,8,9,10,11,
  4,5,6,7,8,9,10,11,
  5,6,7,8,9,10,11,
  6,7,8,9,10,11,
  7,8,9,10,11,
  8,9,10,11,
  9,10,11,
  10,11,
  11};

// ---------------- f32x2 packed-math helpers ----------------
__device__ __forceinline__ void ffma2(unsigned long long& d,
                                      unsigned long long a,
                                      unsigned long long b) {
  asm("fma.rn.f32x2 %0, %1, %2, %0;" : "+l"(d) : "l"(a), "l"(b));
}
__device__ __forceinline__ unsigned long long pack2(float x) {
  unsigned long long r;
  asm("mov.b64 %0, {%1, %1};" : "=l"(r) : "f"(x));
  return r;
}
__device__ __forceinline__ float2 unpack2(unsigned long long u) {
  float2 r;
  asm("mov.b64 {%0, %1}, %2;" : "=f"(r.x), "=f"(r.y) : "l"(u));
  return r;
}

// XOR swizzle on 16-byte-unit index (kills 2-way conflict of stride-32B LDS.128)
#define XSW(u) ((u) ^ (((u) >> 3) & 1))

// ---------------- shared conv body: 68 pairs x 128 px, FFMA2 ----------------
// block = 288 threads: pi=tid>>4 (pair group of 4), pj=tid&15 (8 px each)
template <int C, int SS>
__device__ __forceinline__ void conv_body(const float* __restrict__ X,
                                          const float* __restrict__ W,
                                          const float* __restrict__ bias,
                                          float* __restrict__ Og,
                                          int n, int px0,
                                          float* Ws, float* Xs) {
  const int tid = threadIdx.x;
  const int pi = tid >> 4, pj = tid & 15;

  unsigned long long acc[4][4];
#pragma unroll
  for (int a = 0; a < 4; a++) {
    int p = 4 * pi + a;
    unsigned long long pk = pack2((p < NP) ? bias[p] : 0.0f);
#pragma unroll
    for (int h = 0; h < 4; h++) acc[a][h] = pk;
  }

  const float* Xn = X + (size_t)n * C * SS + px0;

  for (int c0 = 0; c0 < C; c0 += 16) {
    __syncthreads();
#pragma unroll
    for (int r = 0; r < 4; r++) {
      int f = tid + r * 288;                    // f = k*72 + p
      int k = f / NPP, p = f - k * NPP;
      Ws[f] = (p < NP) ? W[p * C + c0 + k] : 0.0f;  // on-the-fly transpose
    }
#pragma unroll
    for (int t = 0; t < 2; t++) {
      int f = tid + t * 288;
      if (f < 512) {
        int c = f >> 5, q = f & 31;
        *(float4*)&Xs[c * 128 + 4 * XSW(q)] =
            *(const float4*)&Xn[(size_t)(c0 + c) * SS + 4 * q];
      }
    }
    __syncthreads();
#pragma unroll
    for (int k = 0; k < 16; k++) {
      const float4 wv4 = *(const float4*)&Ws[k * NPP + 4 * pi];
      const ulonglong2 xA = *(const ulonglong2*)&Xs[k * 128 + 4 * XSW(2 * pj)];
      const ulonglong2 xB = *(const ulonglong2*)&Xs[k * 128 + 4 * XSW(2 * pj + 1)];
      unsigned long long w_[4] = {pack2(wv4.x), pack2(wv4.y), pack2(wv4.z), pack2(wv4.w)};
      unsigned long long x_[4] = {xA.x, xA.y, xB.x, xB.y};
#pragma unroll
      for (int a = 0; a < 4; a++)
#pragma unroll
        for (int h = 0; h < 4; h++) ffma2(acc[a][h], w_[a], x_[h]);
    }
  }

  float* On = Og + (size_t)n * NP * SS + px0 + 8 * pj;
#pragma unroll
  for (int a = 0; a < 4; a++) {
    int p = 4 * pi + a;
    if (p < NP) {
      ulonglong2 v0, v1;
      v0.x = acc[a][0]; v0.y = acc[a][1];
      v1.x = acc[a][2]; v1.y = acc[a][3];
      *(ulonglong2*)&On[(size_t)p * SS] = v0;
      *(ulonglong2*)&On[(size_t)p * SS + 4] = v1;
    }
  }
}

// ---------------- merged conv for stages 0..2 ----------------
__global__ __launch_bounds__(288, 3) void conv_all(
    const float* __restrict__ s0, const float* __restrict__ s1,
    const float* __restrict__ s2, const float* __restrict__ w0,
    const float* __restrict__ w1, const float* __restrict__ w2,
    const float* __restrict__ b0, const float* __restrict__ b1,
    const float* __restrict__ b2) {
  __shared__ __align__(16) float Ws[16 * NPP];
  __shared__ __align__(16) float Xs[16 * 128];
  int bid = blockIdx.x;
  if (bid < 64) {
    conv_body<512, 32 * 32>(s0, w0, b0, g_O0, bid >> 3, (bid & 7) << 7, Ws, Xs);
  } else if (bid < 320) {
    int q = bid - 64;
    conv_body<256, 64 * 64>(s1, w1, b1, g_O1, q >> 5, (q & 31) << 7, Ws, Xs);
  } else {
    int q = bid - 320;
    conv_body<128, 128 * 128>(s2, w2, b2, g_O2, q >> 7, (q & 127) << 7, Ws, Xs);
  }
}

// ---------------- fused: stage3 conv + bilinear pyramid sum + popc vote ----------------
// tile = 8 rows x 16 cols, flat px = row*16+col; thread pj owns px 8pj..8pj+7
__global__ __launch_bounds__(288, 2) void fused_kernel(
    const float* __restrict__ X, const float* __restrict__ W,
    const float* __restrict__ bias, float* __restrict__ out) {
  __shared__ __align__(16) float Ws[16 * NPP];
  __shared__ __align__(16) float Xs[16 * 128];
  __shared__ __align__(16) float sO2[NP * 72];   // 6 rows x 10 cols (pad 12)
  __shared__ __align__(16) float sO1[NP * 32];   // 4 x 6 (pad 8)
  __shared__ __align__(16) float sO0[NP * 12];   // 3 x 4
  __shared__ unsigned sSigns[17 * 32];           // [pi][128 px] nibble bytes
  __shared__ __align__(16) int sMask[12][8];

  const int tid = threadIdx.x;
  const int pi = tid >> 4, pj = tid & 15;
  const int n = blockIdx.y;
  const int ty = blockIdx.x >> 4, tx = blockIdx.x & 15;
  const int y0 = ty << 3, x0 = tx << 4;

  // vote masks (static function of c_I/c_J); one warp, before first sync
  if (tid >= 96 && tid < 108) {
    int k = tid - 96;
    int m[6] = {0, 0, 0, 0, 0, 0};
    for (int p = 0; p < NP; p++) {
      int word = p >> 5, bit = p & 31;
      if (c_I[p] == k) m[word] |= 1 << bit;
      if (c_J[p] == k) m[3 + word] |= 1 << bit;
    }
#pragma unroll
    for (int t = 0; t < 6; t++) sMask[k][t] = m[t];
    sMask[k][6] = k; sMask[k][7] = 0;
  }

  {  // stage O2 region (128x128 src): 6 rows x 10 cols per pair, pad 12
    const float* src = g_O2 + (size_t)n * NP * 16384;
    int by = (y0 >> 1) - 1, bx = (x0 >> 1) - 1;
    for (int i = tid; i < NP * 60; i += 288) {
      int p = i / 60, cell = i - p * 60;
      int rr = cell / 10, cc = cell - rr * 10;
      int sy = min(max(by + rr, 0), 127);
      int sx = min(max(bx + cc, 0), 127);
      sO2[p * 72 + rr * 12 + cc] = src[p * 16384 + sy * 128 + sx];
    }
  }
  {  // stage O1 region (64x64 src): 4 x 6, pad 8
    const float* src = g_O1 + (size_t)n * NP * 4096;
    int by = (y0 >> 2) - 1, bx = (x0 >> 2) - 1;
    for (int i = tid; i < NP * 24; i += 288) {
      int p = i / 24, cell = i - p * 24;
      int rr = cell / 6, cc = cell - rr * 6;
      int sy = min(max(by + rr, 0), 63);
      int sx = min(max(bx + cc, 0), 63);
      sO1[p * 32 + rr * 8 + cc] = src[p * 4096 + sy * 64 + sx];
    }
  }
  {  // stage O0 region (32x32 src): 3 x 4
    const float* src = g_O0 + (size_t)n * NP * 1024;
    int by = (y0 >> 3) - 1, bx = (x0 >> 3) - 1;
    for (int i = tid; i < NP * 12; i += 288) {
      int p = i / 12, cell = i - p * 12;
      int rr = cell >> 2, cc = cell & 3;
      int sy = min(max(by + rr, 0), 31);
      int sx = min(max(bx + cc, 0), 31);
      sO0[p * 12 + rr * 4 + cc] = src[p * 1024 + sy * 32 + sx];
    }
  }

  // ---- stage3 GEMM mainloop (C=64) ----
  unsigned long long acc[4][4];
#pragma unroll
  for (int a = 0; a < 4; a++) {
    int p = 4 * pi + a;
    unsigned long long pk = pack2((p < NP) ? bias[p] : 0.0f);
#pragma unroll
    for (int h = 0; h < 4; h++) acc[a][h] = pk;
  }
  const float* Xn = X + (size_t)n * 64 * 65536;

  for (int c0 = 0; c0 < 64; c0 += 16) {
    __syncthreads();
#pragma unroll
    for (int r = 0; r < 4; r++) {
      int f = tid + r * 288;
      int k = f / NPP, p = f - k * NPP;
      Ws[f] = (p < NP) ? W[p * 64 + c0 + k] : 0.0f;
    }
#pragma unroll
    for (int t = 0; t < 2; t++) {
      int f = tid + t * 288;
      if (f < 512) {
        int c = f >> 5, q = f & 31;
        int rr = q >> 2, c4 = (q & 3) << 2;
        *(float4*)&Xs[c * 128 + 4 * XSW(q)] =
            *(const float4*)&Xn[((size_t)(c0 + c) * 256 + (y0 + rr)) * 256 + x0 + c4];
      }
    }
    __syncthreads();
#pragma unroll
    for (int k = 0; k < 16; k++) {
      const float4 wv4 = *(const float4*)&Ws[k * NPP + 4 * pi];
      const ulonglong2 xA = *(const ulonglong2*)&Xs[k * 128 + 4 * XSW(2 * pj)];
      const ulonglong2 xB = *(const ulonglong2*)&Xs[k * 128 + 4 * XSW(2 * pj + 1)];
      unsigned long long w_[4] = {pack2(wv4.x), pack2(wv4.y), pack2(wv4.z), pack2(wv4.w)};
      unsigned long long x_[4] = {xA.x, xA.y, xB.x, xB.y};
#pragma unroll
      for (int a = 0; a < 4; a++)
#pragma unroll
        for (int h = 0; h < 4; h++) ffma2(acc[a][h], w_[a], x_[h]);
    }
  }

  // ---- epilogue: separable bilinear (octet-shared taps) + sign nibbles ----
  {
    const int r = pj >> 1;          // output row in tile (0..7)
    const int oxb = (pj & 1) << 3;  // column octet base (0 or 8)
    const float WY2[8] = {.75f, .25f, .75f, .25f, .75f, .25f, .75f, .25f};
    const int   RY2[8] = {0, 1, 1, 2, 2, 3, 3, 4};
    const float WY1[8] = {.625f, .875f, .125f, .375f, .625f, .875f, .125f, .375f};
    const int   RY1[8] = {0, 0, 1, 1, 1, 1, 2, 2};
    const float WY0[8] = {.5625f, .6875f, .8125f, .9375f, .0625f, .1875f, .3125f, .4375f};
    const int   RY0[8] = {0, 0, 0, 0, 1, 1, 1, 1};
    const float WX2[8] = {.75f, .25f, .75f, .25f, .75f, .25f, .75f, .25f};
    const int   OX2[8] = {0, 1, 1, 2, 2, 3, 3, 4};
    const float WX1[8] = {.625f, .875f, .125f, .375f, .625f, .875f, .125f, .375f};
    const int   OX1[8] = {0, 0, 1, 1, 1, 1, 2, 2};
    const float WX0[8] = {.5625f, .6875f, .8125f, .9375f, .0625f, .1875f, .3125f, .4375f};
    const int   OX0[8] = {0, 0, 0, 0, 1, 1, 1, 1};

    const int ry2 = RY2[r]; const float wy2 = WY2[r];
    const int ry1 = RY1[r]; const float wy1 = WY1[r];
    const int ry0 = RY0[r]; const float wy0 = WY0[r];
    const int b2 = oxb >> 1, b1 = oxb >> 2, b0 = oxb >> 3;

    unsigned nibLo = 0, nibHi = 0;
    if (pi < 17) {
#pragma unroll
      for (int a = 0; a < 4; a++) {
        int p = 4 * pi + a;
        float v[8];
#pragma unroll
        for (int h = 0; h < 4; h++) {
          float2 t = unpack2(acc[a][h]);
          v[2 * h] = t.x; v[2 * h + 1] = t.y;
        }
        if (p < NP) {
          // L2: y-lerp 6 consecutive taps (vector loads)
          float ty2[6];
          {
            const float* rA = &sO2[p * 72 + ry2 * 12 + b2];
            const float* rB = rA + 12;
            float4 a4 = *(const float4*)rA;  float2 a2 = *(const float2*)(rA + 4);
            float4 b4 = *(const float4*)rB;  float2 b2v = *(const float2*)(rB + 4);
            ty2[0] = a4.x + wy2 * (b4.x - a4.x);
            ty2[1] = a4.y + wy2 * (b4.y - a4.y);
            ty2[2] = a4.z + wy2 * (b4.z - a4.z);
            ty2[3] = a4.w + wy2 * (b4.w - a4.w);
            ty2[4] = a2.x + wy2 * (b2v.x - a2.x);
            ty2[5] = a2.y + wy2 * (b2v.y - a2.y);
          }
          // L1: 4 taps
          float ty1[4];
          {
            const float* rA = &sO1[p * 32 + ry1 * 8 + b1];
            const float* rB = rA + 8;
            float2 a0 = *(const float2*)rA, a1 = *(const float2*)(rA + 2);
            float2 c0v = *(const float2*)rB, c1 = *(const float2*)(rB + 2);
            ty1[0] = a0.x + wy1 * (c0v.x - a0.x);
            ty1[1] = a0.y + wy1 * (c0v.y - a0.y);
            ty1[2] = a1.x + wy1 * (c1.x - a1.x);
            ty1[3] = a1.y + wy1 * (c1.y - a1.y);
          }
          // L0: 3 taps (row float4 + select by b0)
          float ty0[3];
          {
            const float* rA = &sO0[p * 12 + (ry0 << 2)];
            float4 a4 = *(const float4*)rA;
            float4 b4 = *(const float4*)(rA + 4);
            float a0 = b0 ? a4.y : a4.x, a1 = b0 ? a4.z : a4.y, a2 = b0 ? a4.w : a4.z;
            float c0v = b0 ? b4.y : b4.x, c1 = b0 ? b4.z : b4.y, c2 = b0 ? b4.w : b4.z;
            ty0[0] = a0 + wy0 * (c0v - a0);
            ty0[1] = a1 + wy0 * (c1 - a1);
            ty0[2] = a2 + wy0 * (c2 - a2);
          }
#pragma unroll
          for (int q = 0; q < 8; q++) {
            float lo2 = ty2[OX2[q]], hi2 = ty2[OX2[q] + 1];
            float lo1 = ty1[OX1[q]], hi1 = ty1[OX1[q] + 1];
            float lo0 = ty0[OX0[q]], hi0 = ty0[OX0[q] + 1];
            v[q] += lo2 + WX2[q] * (hi2 - lo2);
            v[q] += lo1 + WX1[q] * (hi1 - lo1);
            v[q] += lo0 + WX0[q] * (hi0 - lo0);
          }
        }
#pragma unroll
        for (int q = 0; q < 8; q++) {
          unsigned bit = (v[q] > 0.0f) ? 1u : 0u;
          if (q < 4) nibLo |= bit << ((q << 3) + a);
          else       nibHi |= bit << (((q - 4) << 3) + a);
        }
      }
      sSigns[pi * 32 + 2 * pj]     = nibLo;
      sSigns[pi * 32 + 2 * pj + 1] = nibHi;
    }
  }
  __syncthreads();

  // ---- vote via popcount masks, direct coalesced store ----
  if (tid < 128) {
    const unsigned char* sb = (const unsigned char*)sSigns;
    unsigned sw0 = 0, sw1 = 0;
#pragma unroll
    for (int g = 0; g < 8; g++) sw0 |= (unsigned)sb[g * 128 + tid] << (4 * g);
#pragma unroll
    for (int g = 8; g < 16; g++) sw1 |= (unsigned)sb[g * 128 + tid] << (4 * (g - 8));
    unsigned sw2 = sb[16 * 128 + tid];
    int row = tid >> 4, col = tid & 15;
    float* op = out + (size_t)n * 12 * 65536 + (y0 + row) * 256 + (x0 + col);
#pragma unroll
    for (int k = 0; k < 12; k++) {
      int4 A = *(const int4*)&sMask[k][0];
      int4 B = *(const int4*)&sMask[k][4];
      int cnt = __popc(sw0 & (unsigned)A.x) + __popc(sw1 & (unsigned)A.y) +
                __popc(sw2 & (unsigned)A.z) - __popc(sw0 & (unsigned)A.w) -
                __popc(sw1 & (unsigned)B.x) - __popc(sw2 & (unsigned)B.y) + k;
      op[(size_t)k << 16] = (float)cnt;
    }
  }
}

// ---------------- launcher ----------------
extern "C" void kernel_launch(void* const* d_in, const int* in_sizes, int n_in,
                              void* d_out, int out_size) {
  const float* st[4] = {0, 0, 0, 0};
  const float* w[4] = {0, 0, 0, 0};
  const float* bb[4] = {0, 0, 0, 0};
  int bc = 0;
  for (int i = 0; i < n_in; i++) {
    switch (in_sizes[i]) {
      case 4194304:  st[0] = (const float*)d_in[i]; break;  // 8*512*32*32
      case 8388608:  st[1] = (const float*)d_in[i]; break;  // 8*256*64*64
      case 16777216: st[2] = (const float*)d_in[i]; break;  // 8*128*128*128
      case 33554432: st[3] = (const float*)d_in[i]; break;  // 8*64*256*256
      case 33792: w[0] = (const float*)d_in[i]; break;      // 66*512
      case 16896: w[1] = (const float*)d_in[i]; break;      // 66*256
      case 8448:  w[2] = (const float*)d_in[i]; break;      // 66*128
      case 4224:  w[3] = (const float*)d_in[i]; break;      // 66*64
      case 66:
        if (bc < 4) bb[bc++] = (const float*)d_in[i];       // b0..b3 in order
        break;
      default: break;  // last_only (==1 always per setup_inputs)
    }
  }

  conv_all<<<1344, 288>>>(st[0], st[1], st[2], w[0], w[1], w[2],
                          bb[0], bb[1], bb[2]);
  fused_kernel<<<dim3(512, 8), 288>>>(st[3], w[3], bb[3], (float*)d_out);
}

// round 5
// speedup vs baseline: 1.1367x; 1.0531x over previous
#include <cuda_runtime.h>

#define NP  66
#define NPP 72

// ---------------- scratch (no allocations allowed) ----------------
__device__ __align__(16) float g_O0[8 * NP * 32 * 32];
__device__ __align__(16) float g_O1[8 * NP * 64 * 64];
__device__ __align__(16) float g_O2[8 * NP * 128 * 128];

__constant__ int c_I[NP] = {
  0,0,0,0,0,0,0,0,0,0,0,
  1,1,1,1,1,1,1,1,1,1,
  2,2,2,2,2,2,2,2,2,
  3,3,3,3,3,3,3,3,
  4,4,4,4,4,4,4,
  5,5,5,5,5,5,
  6,6,6,6,6,
  7,7,7,7,
  8,8,8,
  9,9,
  10};
__constant__ int c_J[NP] = {
  1,2,3,4,5,6,7,8,9,10,11,
  2,3,4,5,6,7,8,9,10,11,
  3,4,5,6,7,8,9,10,11,
  4,5,6,7,8,9,10,11,
  5,6,7,8,9,10,11,
  6,7,8,9,10,11,
  7,8,9,10,11,
  8,9,10,11,
  9,10,11,
  10,11,
  11};

// ---------------- f32x2 packed-math helpers ----------------
__device__ __forceinline__ void ffma2(unsigned long long& d,
                                      unsigned long long a,
                                      unsigned long long b) {
  asm("fma.rn.f32x2 %0, %1, %2, %0;" : "+l"(d) : "l"(a), "l"(b));
}
__device__ __forceinline__ unsigned long long pack2(float x) {
  unsigned long long r;
  asm("mov.b64 %0, {%1, %1};" : "=l"(r) : "f"(x));
  return r;
}
__device__ __forceinline__ float2 unpack2(unsigned long long u) {
  float2 r;
  asm("mov.b64 {%0, %1}, %2;" : "=f"(r.x), "=f"(r.y) : "l"(u));
  return r;
}

// XOR swizzle on 16-byte-unit index (kills 2-way conflict of stride-32B LDS.128)
#define XSW(u) ((u) ^ (((u) >> 3) & 1))

#define COMPUTE16()                                                            \
  _Pragma("unroll")                                                            \
  for (int k = 0; k < 16; k++) {                                               \
    const float4 wv4 = *(const float4*)&Ws[k * NPP + 4 * pi];                  \
    const ulonglong2 xA = *(const ulonglong2*)&Xs[k * 128 + xsA];              \
    const ulonglong2 xB = *(const ulonglong2*)&Xs[k * 128 + xsB];              \
    unsigned long long w_[4] = {pack2(wv4.x), pack2(wv4.y), pack2(wv4.z),      \
                                pack2(wv4.w)};                                 \
    unsigned long long x_[4] = {xA.x, xA.y, xB.x, xB.y};                       \
    _Pragma("unroll")                                                          \
    for (int a = 0; a < 4; a++)                                                \
      _Pragma("unroll")                                                        \
      for (int h = 0; h < 4; h++) ffma2(acc[a][h], w_[a], x_[h]);              \
  }

// ---------------- shared conv body: 68 pairs x 128 px, FFMA2, reg-prefetch ----
// block = 288 threads: pi=tid>>4 (pair group of 4), pj=tid&15 (8 px each)
template <int C, int SS>
__device__ __forceinline__ void conv_body(const float* __restrict__ X,
                                          const float* __restrict__ W,
                                          const float* __restrict__ bias,
                                          float* __restrict__ Og,
                                          int n, int px0,
                                          float* Ws, float* Xs) {
  const int tid = threadIdx.x;
  const int pi = tid >> 4, pj = tid & 15;

  unsigned long long acc[4][4];
#pragma unroll
  for (int a = 0; a < 4; a++) {
    int p = 4 * pi + a;
    unsigned long long pk = pack2((p < NP) ? bias[p] : 0.0f);
#pragma unroll
    for (int h = 0; h < 4; h++) acc[a][h] = pk;
  }

  // loop-invariant slot addressing
  const int c_a = tid >> 5, q_a = tid & 31;
  const int f_b = tid + 288;
  const int c_b = f_b >> 5, q_b = f_b & 31;
  const bool has_b = (tid < 224);
  int wk[4], wp[4];
#pragma unroll
  for (int r = 0; r < 4; r++) {
    int f = tid + r * 288;
    wk[r] = f / NPP; wp[r] = f - wk[r] * NPP;
  }
  const int xdA = c_a * 128 + 4 * XSW(q_a);
  const int xdB = c_b * 128 + 4 * XSW(q_b);
  const int xsA = 4 * XSW(2 * pj), xsB = 4 * XSW(2 * pj + 1);

  const float* Xn = X + (size_t)n * C * SS + px0;
  const float* xpA = Xn + (size_t)c_a * SS + 4 * q_a;
  const float* xpB = Xn + (size_t)c_b * SS + 4 * q_b;

  float4 pxA, pxB;
  float pw[4];
  pxA = *(const float4*)xpA;
  if (has_b) pxB = *(const float4*)xpB;
#pragma unroll
  for (int r = 0; r < 4; r++) pw[r] = (wp[r] < NP) ? W[wp[r] * C + wk[r]] : 0.0f;

  const int NIT = C / 16;
  for (int i = 0; i < NIT; i++) {
    __syncthreads();
#pragma unroll
    for (int r = 0; r < 4; r++) Ws[tid + r * 288] = pw[r];
    *(float4*)&Xs[xdA] = pxA;
    if (has_b) *(float4*)&Xs[xdB] = pxB;
    __syncthreads();
    if (i + 1 < NIT) {
      int c0n = (i + 1) * 16;
      pxA = *(const float4*)(xpA + (size_t)c0n * SS);
      if (has_b) pxB = *(const float4*)(xpB + (size_t)c0n * SS);
#pragma unroll
      for (int r = 0; r < 4; r++)
        pw[r] = (wp[r] < NP) ? W[wp[r] * C + c0n + wk[r]] : 0.0f;
    }
    COMPUTE16();
  }

  float* On = Og + (size_t)n * NP * SS + px0 + 8 * pj;
#pragma unroll
  for (int a = 0; a < 4; a++) {
    int p = 4 * pi + a;
    if (p < NP) {
      ulonglong2 v0, v1;
      v0.x = acc[a][0]; v0.y = acc[a][1];
      v1.x = acc[a][2]; v1.y = acc[a][3];
      *(ulonglong2*)&On[(size_t)p * SS] = v0;
      *(ulonglong2*)&On[(size_t)p * SS + 4] = v1;
    }
  }
}

// ---------------- merged conv for stages 0..2 ----------------
__global__ __launch_bounds__(288, 3) void conv_all(
    const float* __restrict__ s0, const float* __restrict__ s1,
    const float* __restrict__ s2, const float* __restrict__ w0,
    const float* __restrict__ w1, const float* __restrict__ w2,
    const float* __restrict__ b0, const float* __restrict__ b1,
    const float* __restrict__ b2) {
  __shared__ __align__(16) float Ws[16 * NPP];
  __shared__ __align__(16) float Xs[16 * 128];
  int bid = blockIdx.x;
  if (bid < 64) {
    conv_body<512, 32 * 32>(s0, w0, b0, g_O0, bid >> 3, (bid & 7) << 7, Ws, Xs);
  } else if (bid < 320) {
    int q = bid - 64;
    conv_body<256, 64 * 64>(s1, w1, b1, g_O1, q >> 5, (q & 31) << 7, Ws, Xs);
  } else {
    int q = bid - 320;
    conv_body<128, 128 * 128>(s2, w2, b2, g_O2, q >> 7, (q & 127) << 7, Ws, Xs);
  }
}

// ---------------- fused: stage3 conv + bilinear pyramid sum + popc vote ----------------
// tile = 8 rows x 16 cols, flat px = row*16+col; thread pj owns px 8pj..8pj+7
__global__ __launch_bounds__(288, 2) void fused_kernel(
    const float* __restrict__ X, const float* __restrict__ W,
    const float* __restrict__ bias, float* __restrict__ out) {
  __shared__ __align__(16) float Ws[16 * NPP];
  __shared__ __align__(16) float Xs[16 * 128];
  __shared__ __align__(16) float sO2[NP * 72];   // 6 rows x 10 cols (pad 12)
  __shared__ __align__(16) float sO1[NP * 32];   // 4 x 6 (pad 8)
  __shared__ __align__(16) float sO0[NP * 12];   // 3 x 4
  __shared__ unsigned sSigns[17 * 32];           // [pi][128 px] nibble bytes
  __shared__ __align__(16) int sMask[12][8];

  const int tid = threadIdx.x;
  const int pi = tid >> 4, pj = tid & 15;
  const int n = blockIdx.y;
  const int ty = blockIdx.x >> 4, tx = blockIdx.x & 15;
  const int y0 = ty << 3, x0 = tx << 4;

  // vote masks (static function of c_I/c_J); one warp, before first sync
  if (tid >= 96 && tid < 108) {
    int k = tid - 96;
    int m[6] = {0, 0, 0, 0, 0, 0};
    for (int p = 0; p < NP; p++) {
      int word = p >> 5, bit = p & 31;
      if (c_I[p] == k) m[word] |= 1 << bit;
      if (c_J[p] == k) m[3 + word] |= 1 << bit;
    }
#pragma unroll
    for (int t = 0; t < 6; t++) sMask[k][t] = m[t];
    sMask[k][6] = k; sMask[k][7] = 0;
  }

  {  // stage O2 region (128x128 src): 6 rows x 10 cols per pair, pad 12
    const float* src = g_O2 + (size_t)n * NP * 16384;
    int by = (y0 >> 1) - 1, bx = (x0 >> 1) - 1;
    for (int i = tid; i < NP * 60; i += 288) {
      int p = i / 60, cell = i - p * 60;
      int rr = cell / 10, cc = cell - rr * 10;
      int sy = min(max(by + rr, 0), 127);
      int sx = min(max(bx + cc, 0), 127);
      sO2[p * 72 + rr * 12 + cc] = src[p * 16384 + sy * 128 + sx];
    }
  }
  {  // stage O1 region (64x64 src): 4 x 6, pad 8
    const float* src = g_O1 + (size_t)n * NP * 4096;
    int by = (y0 >> 2) - 1, bx = (x0 >> 2) - 1;
    for (int i = tid; i < NP * 24; i += 288) {
      int p = i / 24, cell = i - p * 24;
      int rr = cell / 6, cc = cell - rr * 6;
      int sy = min(max(by + rr, 0), 63);
      int sx = min(max(bx + cc, 0), 63);
      sO1[p * 32 + rr * 8 + cc] = src[p * 4096 + sy * 64 + sx];
    }
  }
  {  // stage O0 region (32x32 src): 3 x 4
    const float* src = g_O0 + (size_t)n * NP * 1024;
    int by = (y0 >> 3) - 1, bx = (x0 >> 3) - 1;
    for (int i = tid; i < NP * 12; i += 288) {
      int p = i / 12, cell = i - p * 12;
      int rr = cell >> 2, cc = cell & 3;
      int sy = min(max(by + rr, 0), 31);
      int sx = min(max(bx + cc, 0), 31);
      sO0[p * 12 + rr * 4 + cc] = src[p * 1024 + sy * 32 + sx];
    }
  }

  // ---- stage3 GEMM mainloop (C=64), register-prefetch pipeline ----
  unsigned long long acc[4][4];
#pragma unroll
  for (int a = 0; a < 4; a++) {
    int p = 4 * pi + a;
    unsigned long long pk = pack2((p < NP) ? bias[p] : 0.0f);
#pragma unroll
    for (int h = 0; h < 4; h++) acc[a][h] = pk;
  }

  const int c_a = tid >> 5, q_a = tid & 31;
  const int f_b = tid + 288;
  const int c_b = f_b >> 5, q_b = f_b & 31;
  const bool has_b = (tid < 224);
  int wk[4], wp[4];
#pragma unroll
  for (int r = 0; r < 4; r++) {
    int f = tid + r * 288;
    wk[r] = f / NPP; wp[r] = f - wk[r] * NPP;
  }
  const int xdA = c_a * 128 + 4 * XSW(q_a);
  const int xdB = c_b * 128 + 4 * XSW(q_b);
  const int xsA = 4 * XSW(2 * pj), xsB = 4 * XSW(2 * pj + 1);

  const float* Xn = X + (size_t)n * 64 * 65536;
  const float* xpA = Xn + (size_t)c_a * 65536 + (y0 + (q_a >> 2)) * 256 + x0 + ((q_a & 3) << 2);
  const float* xpB = Xn + (size_t)c_b * 65536 + (y0 + (q_b >> 2)) * 256 + x0 + ((q_b & 3) << 2);

  float4 pxA, pxB;
  float pw[4];
  pxA = *(const float4*)xpA;
  if (has_b) pxB = *(const float4*)xpB;
#pragma unroll
  for (int r = 0; r < 4; r++) pw[r] = (wp[r] < NP) ? W[wp[r] * 64 + wk[r]] : 0.0f;

  for (int i = 0; i < 4; i++) {
    __syncthreads();
#pragma unroll
    for (int r = 0; r < 4; r++) Ws[tid + r * 288] = pw[r];
    *(float4*)&Xs[xdA] = pxA;
    if (has_b) *(float4*)&Xs[xdB] = pxB;
    __syncthreads();
    if (i < 3) {
      int c0n = (i + 1) * 16;
      pxA = *(const float4*)(xpA + (size_t)c0n * 65536);
      if (has_b) pxB = *(const float4*)(xpB + (size_t)c0n * 65536);
#pragma unroll
      for (int r = 0; r < 4; r++)
        pw[r] = (wp[r] < NP) ? W[wp[r] * 64 + c0n + wk[r]] : 0.0f;
    }
    COMPUTE16();
  }

  // ---- epilogue: separable bilinear (octet-shared taps) + sign nibbles ----
  {
    const int r = pj >> 1;          // output row in tile (0..7)
    const int oxb = (pj & 1) << 3;  // column octet base (0 or 8)
    const float WY2[8] = {.75f, .25f, .75f, .25f, .75f, .25f, .75f, .25f};
    const int   RY2[8] = {0, 1, 1, 2, 2, 3, 3, 4};
    const float WY1[8] = {.625f, .875f, .125f, .375f, .625f, .875f, .125f, .375f};
    const int   RY1[8] = {0, 0, 1, 1, 1, 1, 2, 2};
    const float WY0[8] = {.5625f, .6875f, .8125f, .9375f, .0625f, .1875f, .3125f, .4375f};
    const int   RY0[8] = {0, 0, 0, 0, 1, 1, 1, 1};
    const float WX2[8] = {.75f, .25f, .75f, .25f, .75f, .25f, .75f, .25f};
    const int   OX2[8] = {0, 1, 1, 2, 2, 3, 3, 4};
    const float WX1[8] = {.625f, .875f, .125f, .375f, .625f, .875f, .125f, .375f};
    const int   OX1[8] = {0, 0, 1, 1, 1, 1, 2, 2};
    const float WX0[8] = {.5625f, .6875f, .8125f, .9375f, .0625f, .1875f, .3125f, .4375f};
    const int   OX0[8] = {0, 0, 0, 0, 1, 1, 1, 1};

    const int ry2 = RY2[r]; const float wy2 = WY2[r];
    const int ry1 = RY1[r]; const float wy1 = WY1[r];
    const int ry0 = RY0[r]; const float wy0 = WY0[r];
    const int b2 = oxb >> 1, b1 = oxb >> 2, b0 = oxb >> 3;

    unsigned nibLo = 0, nibHi = 0;
    if (pi < 17) {
#pragma unroll
      for (int a = 0; a < 4; a++) {
        int p = 4 * pi + a;
        float v[8];
#pragma unroll
        for (int h = 0; h < 4; h++) {
          float2 t = unpack2(acc[a][h]);
          v[2 * h] = t.x; v[2 * h + 1] = t.y;
        }
        if (p < NP) {
          // L2: y-lerp 6 consecutive taps (vector loads)
          float ty2[6];
          {
            const float* rA = &sO2[p * 72 + ry2 * 12 + b2];
            const float* rB = rA + 12;
            float4 a4 = *(const float4*)rA;  float2 a2 = *(const float2*)(rA + 4);
            float4 b4 = *(const float4*)rB;  float2 b2v = *(const float2*)(rB + 4);
            ty2[0] = a4.x + wy2 * (b4.x - a4.x);
            ty2[1] = a4.y + wy2 * (b4.y - a4.y);
            ty2[2] = a4.z + wy2 * (b4.z - a4.z);
            ty2[3] = a4.w + wy2 * (b4.w - a4.w);
            ty2[4] = a2.x + wy2 * (b2v.x - a2.x);
            ty2[5] = a2.y + wy2 * (b2v.y - a2.y);
          }
          // L1: 4 taps
          float ty1[4];
          {
            const float* rA = &sO1[p * 32 + ry1 * 8 + b1];
            const float* rB = rA + 8;
            float2 a0 = *(const float2*)rA, a1 = *(const float2*)(rA + 2);
            float2 c0v = *(const float2*)rB, c1 = *(const float2*)(rB + 2);
            ty1[0] = a0.x + wy1 * (c0v.x - a0.x);
            ty1[1] = a0.y + wy1 * (c0v.y - a0.y);
            ty1[2] = a1.x + wy1 * (c1.x - a1.x);
            ty1[3] = a1.y + wy1 * (c1.y - a1.y);
          }
          // L0: 3 taps (row float4 + select by b0)
          float ty0[3];
          {
            const float* rA = &sO0[p * 12 + (ry0 << 2)];
            float4 a4 = *(const float4*)rA;
            float4 b4 = *(const float4*)(rA + 4);
            float a0 = b0 ? a4.y : a4.x, a1 = b0 ? a4.z : a4.y, a2 = b0 ? a4.w : a4.z;
            float c0v = b0 ? b4.y : b4.x, c1 = b0 ? b4.z : b4.y, c2 = b0 ? b4.w : b4.z;
            ty0[0] = a0 + wy0 * (c0v - a0);
            ty0[1] = a1 + wy0 * (c1 - a1);
            ty0[2] = a2 + wy0 * (c2 - a2);
          }
#pragma unroll
          for (int q = 0; q < 8; q++) {
            float lo2 = ty2[OX2[q]], hi2 = ty2[OX2[q] + 1];
            float lo1 = ty1[OX1[q]], hi1 = ty1[OX1[q] + 1];
            float lo0 = ty0[OX0[q]], hi0 = ty0[OX0[q] + 1];
            v[q] += lo2 + WX2[q] * (hi2 - lo2);
            v[q] += lo1 + WX1[q] * (hi1 - lo1);
            v[q] += lo0 + WX0[q] * (hi0 - lo0);
          }
        }
#pragma unroll
        for (int q = 0; q < 8; q++) {
          unsigned bit = (v[q] > 0.0f) ? 1u : 0u;
          if (q < 4) nibLo |= bit << ((q << 3) + a);
          else       nibHi |= bit << (((q - 4) << 3) + a);
        }
      }
      sSigns[pi * 32 + 2 * pj]     = nibLo;
      sSigns[pi * 32 + 2 * pj + 1] = nibHi;
    }
  }
  __syncthreads();

  // ---- vote via popcount masks, direct coalesced store ----
  if (tid < 128) {
    const unsigned char* sb = (const unsigned char*)sSigns;
    unsigned sw0 = 0, sw1 = 0;
#pragma unroll
    for (int g = 0; g < 8; g++) sw0 |= (unsigned)sb[g * 128 + tid] << (4 * g);
#pragma unroll
    for (int g = 8; g < 16; g++) sw1 |= (unsigned)sb[g * 128 + tid] << (4 * (g - 8));
    unsigned sw2 = sb[16 * 128 + tid];
    int row = tid >> 4, col = tid & 15;
    float* op = out + (size_t)n * 12 * 65536 + (y0 + row) * 256 + (x0 + col);
#pragma unroll
    for (int k = 0; k < 12; k++) {
      int4 A = *(const int4*)&sMask[k][0];
      int4 B = *(const int4*)&sMask[k][4];
      int cnt = __popc(sw0 & (unsigned)A.x) + __popc(sw1 & (unsigned)A.y) +
                __popc(sw2 & (unsigned)A.z) - __popc(sw0 & (unsigned)A.w) -
                __popc(sw1 & (unsigned)B.x) - __popc(sw2 & (unsigned)B.y) + k;
      op[(size_t)k << 16] = (float)cnt;
    }
  }
}

// ---------------- launcher ----------------
extern "C" void kernel_launch(void* const* d_in, const int* in_sizes, int n_in,
                              void* d_out, int out_size) {
  const float* st[4] = {0, 0, 0, 0};
  const float* w[4] = {0, 0, 0, 0};
  const float* bb[4] = {0, 0, 0, 0};
  int bc = 0;
  for (int i = 0; i < n_in; i++) {
    switch (in_sizes[i]) {
      case 4194304:  st[0] = (const float*)d_in[i]; break;  // 8*512*32*32
      case 8388608:  st[1] = (const float*)d_in[i]; break;  // 8*256*64*64
      case 16777216: st[2] = (const float*)d_in[i]; break;  // 8*128*128*128
      case 33554432: st[3] = (const float*)d_in[i]; break;  // 8*64*256*256
      case 33792: w[0] = (const float*)d_in[i]; break;      // 66*512
      case 16896: w[1] = (const float*)d_in[i]; break;      // 66*256
      case 8448:  w[2] = (const float*)d_in[i]; break;      // 66*128
      case 4224:  w[3] = (const float*)d_in[i]; break;      // 66*64
      case 66:
        if (bc < 4) bb[bc++] = (const float*)d_in[i];       // b0..b3 in order
        break;
      default: break;  // last_only (==1 always per setup_inputs)
    }
  }

  conv_all<<<1344, 288>>>(st[0], st[1], st[2], w[0], w[1], w[2],
                          bb[0], bb[1], bb[2]);
  fused_kernel<<<dim3(512, 8), 288>>>(st[3], w[3], bb[3], (float*)d_out);
}

// round 6
// speedup vs baseline: 1.3192x; 1.1606x over previous
#include <cuda_runtime.h>

#define NP  66
#define NPP 72

// ---------------- scratch (no allocations allowed) ----------------
__device__ __align__(16) float g_O0[8 * NP * 32 * 32];
__device__ __align__(16) float g_O1[8 * NP * 64 * 64];
__device__ __align__(16) float g_O2[8 * NP * 128 * 128];

__constant__ int c_I[NP] = {
  0,0,0,0,0,0,0,0,0,0,0,
  1,1,1,1,1,1,1,1,1,1,
  2,2,2,2,2,2,2,2,2,
  3,3,3,3,3,3,3,3,
  4,4,4,4,4,4,4,
  5,5,5,5,5,5,
  6,6,6,6,6,
  7,7,7,7,
  8,8,8,
  9,9,
  10};
__constant__ int c_J[NP] = {
  1,2,3,4,5,6,7,8,9,10,11,
  2,3,4,5,6,7,8,9,10,11,
  3,4,5,6,7,8,9,10,11,
  4,5,6,7,8,9,10,11,
  5,6,7,8,9,10,11,
  6,7,8,9,10,11,
  7,8,9,10,11,
  8,9,10,11,
  9,10,11,
  10,11,
  11};

// ---------------- helpers ----------------
__device__ __forceinline__ void ffma2(unsigned long long& d,
                                      unsigned long long a,
                                      unsigned long long b) {
  asm("fma.rn.f32x2 %0, %1, %2, %0;" : "+l"(d) : "l"(a), "l"(b));
}
__device__ __forceinline__ unsigned long long pack2(float x) {
  unsigned long long r;
  asm("mov.b64 %0, {%1, %1};" : "=l"(r) : "f"(x));
  return r;
}
__device__ __forceinline__ float2 unpack2(unsigned long long u) {
  float2 r;
  asm("mov.b64 {%0, %1}, %2;" : "=f"(r.x), "=f"(r.y) : "l"(u));
  return r;
}
__device__ __forceinline__ unsigned su32(const void* p) {
  return (unsigned)__cvta_generic_to_shared(p);
}
__device__ __forceinline__ void cpa16(unsigned dst, const void* src) {
  asm volatile("cp.async.cg.shared.global [%0], [%1], 16;" :: "r"(dst), "l"(src));
}
__device__ __forceinline__ void cpa4(unsigned dst, const void* src) {
  asm volatile("cp.async.ca.shared.global [%0], [%1], 4;" :: "r"(dst), "l"(src));
}
#define CPA_COMMIT() asm volatile("cp.async.commit_group;" ::: "memory")
#define CPA_WAIT(n)  asm volatile("cp.async.wait_group %0;" :: "n"(n) : "memory")

// XOR swizzle on 16-byte-unit index (kills 2-way conflict of stride-32B LDS.128)
#define XSW(u) ((u) ^ (((u) >> 3) & 1))

// compute one 8-channel chunk from buffer base pointers
#define COMPUTE8(Wb, Xb)                                                       \
  _Pragma("unroll")                                                            \
  for (int k = 0; k < 8; k++) {                                                \
    const float4 wv4 = *(const float4*)&(Wb)[k * NPP + 4 * pi];                \
    const ulonglong2 xA = *(const ulonglong2*)&(Xb)[k * 128 + xsA];            \
    const ulonglong2 xB = *(const ulonglong2*)&(Xb)[k * 128 + xsB];            \
    unsigned long long w_[4] = {pack2(wv4.x), pack2(wv4.y), pack2(wv4.z),      \
                                pack2(wv4.w)};                                 \
    unsigned long long x_[4] = {xA.x, xA.y, xB.x, xB.y};                       \
    _Pragma("unroll")                                                          \
    for (int a = 0; a < 4; a++)                                                \
      _Pragma("unroll")                                                        \
      for (int h = 0; h < 4; h++) ffma2(acc[a][h], w_[a], x_[h]);              \
  }

// ---------------- conv body: 66 pairs x 128 px, cp.async double-buffer -------
// block = 288 threads: pi=tid>>4 (pair group of 4), pj=tid&15 (8 px each)
// Ws: [2][8*NPP], Xs: [2][8*128]
template <int C, int SS>
__device__ __forceinline__ void conv_body(const float* __restrict__ X,
                                          const float* __restrict__ W,
                                          const float* __restrict__ bias,
                                          float* __restrict__ Og,
                                          int n, int px0,
                                          float* Ws, float* Xs) {
  const int tid = threadIdx.x;
  const int pi = tid >> 4, pj = tid & 15;
  const int xsA = 4 * XSW(2 * pj), xsB = 4 * XSW(2 * pj + 1);

  unsigned long long acc[4][4];
#pragma unroll
  for (int a = 0; a < 4; a++) {
    int p = 4 * pi + a;
    unsigned long long pk = pack2((p < NP) ? bias[p] : 0.0f);
#pragma unroll
    for (int h = 0; h < 4; h++) acc[a][h] = pk;
  }

  // X slots: one 16B per thread (tid<256): c=tid>>5, q=tid&31
  const bool hasx = tid < 256;
  const int c_ = tid >> 5, q_ = tid & 31;
  const unsigned xd0 = su32(&Xs[c_ * 128 + 4 * XSW(q_)]);
  const float* xsrc = X + (size_t)n * C * SS + px0 + (size_t)c_ * SS + 4 * q_;

  // W slots (transpose in flight): s = k*66+p, s in [0,528)
  const int ka = tid / 66, pa = tid - 66 * ka;          // slot a: always valid
  const int sb = tid + 288;
  const bool hasb = sb < 528;
  const int kb = sb / 66, pb = sb - 66 * kb;
  const unsigned wda0 = su32(&Ws[ka * NPP + pa]);
  const unsigned wdb0 = su32(&Ws[kb * NPP + pb]);
  const float* wsa = W + pa * C + ka;
  const float* wsb = W + pb * C + kb;

  // zero the pad slots (p in 66..71) of both buffers, once
  if (tid < 96) {
    int b = tid / 48, r = tid - 48 * b;
    int k = r / 6, p = 66 + (r - 6 * k);
    Ws[b * (8 * NPP) + k * NPP + p] = 0.0f;
  }

  // preload chunk 0
  if (hasx) cpa16(xd0, xsrc);
  cpa4(wda0, wsa);
  if (hasb) cpa4(wdb0, wsb);
  CPA_COMMIT();

  const int NIT = C / 8;
  for (int i = 0; i < NIT; i++) {
    if (i + 1 < NIT) {
      int b = (i + 1) & 1, c0 = (i + 1) * 8;
      if (hasx) cpa16(xd0 + b * 4096, xsrc + (size_t)c0 * SS);
      cpa4(wda0 + b * (8 * NPP * 4), wsa + c0);
      if (hasb) cpa4(wdb0 + b * (8 * NPP * 4), wsb + c0);
      CPA_COMMIT();
      CPA_WAIT(1);
    } else {
      CPA_WAIT(0);
    }
    __syncthreads();
    {
      const float* Wb = Ws + (i & 1) * (8 * NPP);
      const float* Xb = Xs + (i & 1) * (8 * 128);
      COMPUTE8(Wb, Xb);
    }
    __syncthreads();
  }

  float* On = Og + (size_t)n * NP * SS + px0 + 8 * pj;
#pragma unroll
  for (int a = 0; a < 4; a++) {
    int p = 4 * pi + a;
    if (p < NP) {
      ulonglong2 v0, v1;
      v0.x = acc[a][0]; v0.y = acc[a][1];
      v1.x = acc[a][2]; v1.y = acc[a][3];
      *(ulonglong2*)&On[(size_t)p * SS] = v0;
      *(ulonglong2*)&On[(size_t)p * SS + 4] = v1;
    }
  }
}

// ---------------- merged conv for stages 0..2 ----------------
__global__ __launch_bounds__(288, 3) void conv_all(
    const float* __restrict__ s0, const float* __restrict__ s1,
    const float* __restrict__ s2, const float* __restrict__ w0,
    const float* __restrict__ w1, const float* __restrict__ w2,
    const float* __restrict__ b0, const float* __restrict__ b1,
    const float* __restrict__ b2) {
  __shared__ __align__(16) float Ws[2 * 8 * NPP];
  __shared__ __align__(16) float Xs[2 * 8 * 128];
  int bid = blockIdx.x;
  if (bid < 64) {
    conv_body<512, 32 * 32>(s0, w0, b0, g_O0, bid >> 3, (bid & 7) << 7, Ws, Xs);
  } else if (bid < 320) {
    int q = bid - 64;
    conv_body<256, 64 * 64>(s1, w1, b1, g_O1, q >> 5, (q & 31) << 7, Ws, Xs);
  } else {
    int q = bid - 320;
    conv_body<128, 128 * 128>(s2, w2, b2, g_O2, q >> 7, (q & 127) << 7, Ws, Xs);
  }
}

// ---------------- fused: stage3 conv + bilinear pyramid sum + popc vote ------
// tile = 8 rows x 16 cols, flat px = row*16+col; thread pj owns px 8pj..8pj+7
__global__ __launch_bounds__(288, 2) void fused_kernel(
    const float* __restrict__ X, const float* __restrict__ W,
    const float* __restrict__ bias, float* __restrict__ out) {
  __shared__ __align__(16) float Ws[2 * 8 * NPP];
  __shared__ __align__(16) float Xs[2 * 8 * 128];
  __shared__ __align__(16) float sO2[NP * 72];   // 6 rows x 10 cols (pad 12)
  __shared__ __align__(16) float sO1[NP * 32];   // 4 x 6 (pad 8)
  __shared__ __align__(16) float sO0[NP * 12];   // 3 x 4
  __shared__ unsigned sSigns[17 * 32];           // [pi][128 px] nibble bytes
  __shared__ __align__(16) int sMask[12][8];

  const int tid = threadIdx.x;
  const int pi = tid >> 4, pj = tid & 15;
  const int xsA = 4 * XSW(2 * pj), xsB = 4 * XSW(2 * pj + 1);
  const int n = blockIdx.y;
  const int ty = blockIdx.x >> 4, tx = blockIdx.x & 15;
  const int y0 = ty << 3, x0 = tx << 4;

  // ---- mainloop slot addressing ----
  const bool hasx = tid < 256;
  const int c_ = tid >> 5, q_ = tid & 31;
  const unsigned xd0 = su32(&Xs[c_ * 128 + 4 * XSW(q_)]);
  const float* Xn = X + (size_t)n * 64 * 65536;
  const float* xsrc = Xn + (size_t)c_ * 65536 + (y0 + (q_ >> 2)) * 256 + x0 + ((q_ & 3) << 2);
  const int ka = tid / 66, pa = tid - 66 * ka;
  const int sb = tid + 288;
  const bool hasb = sb < 528;
  const int kb = sb / 66, pb = sb - 66 * kb;
  const unsigned wda0 = su32(&Ws[ka * NPP + pa]);
  const unsigned wdb0 = su32(&Ws[kb * NPP + pb]);
  const float* wsa = W + pa * 64 + ka;
  const float* wsb = W + pb * 64 + kb;

  // preload chunk 0 (group 0) — start X flowing ASAP
  if (hasx) cpa16(xd0, xsrc);
  cpa4(wda0, wsa);
  if (hasb) cpa4(wdb0, wsb);
  CPA_COMMIT();

  // ---- sO staging via fire-and-forget cp.async (group 1) ----
  {  // O2 region (128x128 src): 6 rows x 10 cols per pair, pad 12
    const float* src = g_O2 + (size_t)n * NP * 16384;
    int by = (y0 >> 1) - 1, bx = (x0 >> 1) - 1;
    for (int i = tid; i < NP * 60; i += 288) {
      int p = i / 60, cell = i - p * 60;
      int rr = cell / 10, cc = cell - rr * 10;
      int sy = min(max(by + rr, 0), 127);
      int sx = min(max(bx + cc, 0), 127);
      cpa4(su32(&sO2[p * 72 + rr * 12 + cc]), &src[p * 16384 + sy * 128 + sx]);
    }
  }
  {  // O1 region (64x64 src): 4 x 6, pad 8
    const float* src = g_O1 + (size_t)n * NP * 4096;
    int by = (y0 >> 2) - 1, bx = (x0 >> 2) - 1;
    for (int i = tid; i < NP * 24; i += 288) {
      int p = i / 24, cell = i - p * 24;
      int rr = cell / 6, cc = cell - rr * 6;
      int sy = min(max(by + rr, 0), 63);
      int sx = min(max(bx + cc, 0), 63);
      cpa4(su32(&sO1[p * 32 + rr * 8 + cc]), &src[p * 4096 + sy * 64 + sx]);
    }
  }
  {  // O0 region (32x32 src): 3 x 4
    const float* src = g_O0 + (size_t)n * NP * 1024;
    int by = (y0 >> 3) - 1, bx = (x0 >> 3) - 1;
    for (int i = tid; i < NP * 12; i += 288) {
      int p = i / 12, cell = i - p * 12;
      int rr = cell >> 2, cc = cell & 3;
      int sy = min(max(by + rr, 0), 31);
      int sx = min(max(bx + cc, 0), 31);
      cpa4(su32(&sO0[p * 12 + rr * 4 + cc]), &src[p * 1024 + sy * 32 + sx]);
    }
  }
  CPA_COMMIT();

  // vote masks (static function of c_I/c_J)
  if (tid >= 96 && tid < 108) {
    int k = tid - 96;
    int m[6] = {0, 0, 0, 0, 0, 0};
    for (int p = 0; p < NP; p++) {
      int word = p >> 5, bit = p & 31;
      if (c_I[p] == k) m[word] |= 1 << bit;
      if (c_J[p] == k) m[3 + word] |= 1 << bit;
    }
#pragma unroll
    for (int t = 0; t < 6; t++) sMask[k][t] = m[t];
    sMask[k][6] = k; sMask[k][7] = 0;
  }
  // zero the weight pad slots of both buffers
  if (tid < 96) {
    int b = tid / 48, r = tid - 48 * b;
    int k = r / 6, p = 66 + (r - 6 * k);
    Ws[b * (8 * NPP) + k * NPP + p] = 0.0f;
  }

  // ---- stage3 GEMM mainloop (C=64), cp.async double-buffer ----
  unsigned long long acc[4][4];
#pragma unroll
  for (int a = 0; a < 4; a++) {
    int p = 4 * pi + a;
    unsigned long long pk = pack2((p < NP) ? bias[p] : 0.0f);
#pragma unroll
    for (int h = 0; h < 4; h++) acc[a][h] = pk;
  }

  for (int i = 0; i < 8; i++) {
    if (i + 1 < 8) {
      int b = (i + 1) & 1, c0 = (i + 1) * 8;
      if (hasx) cpa16(xd0 + b * 4096, xsrc + (size_t)c0 * 65536);
      cpa4(wda0 + b * (8 * NPP * 4), wsa + c0);
      if (hasb) cpa4(wdb0 + b * (8 * NPP * 4), wsb + c0);
      CPA_COMMIT();
      if (i == 0) { CPA_WAIT(2); }   // allow staging + chunk1 to stay pending
      else        { CPA_WAIT(1); }
    } else {
      CPA_WAIT(0);
    }
    __syncthreads();
    {
      const float* Wb = Ws + (i & 1) * (8 * NPP);
      const float* Xb = Xs + (i & 1) * (8 * 128);
      COMPUTE8(Wb, Xb);
    }
    __syncthreads();
  }

  // ---- epilogue: separable bilinear (octet-shared taps) + sign nibbles ----
  {
    const int r = pj >> 1;          // output row in tile (0..7)
    const int oxb = (pj & 1) << 3;  // column octet base (0 or 8)
    const float WY2[8] = {.75f, .25f, .75f, .25f, .75f, .25f, .75f, .25f};
    const int   RY2[8] = {0, 1, 1, 2, 2, 3, 3, 4};
    const float WY1[8] = {.625f, .875f, .125f, .375f, .625f, .875f, .125f, .375f};
    const int   RY1[8] = {0, 0, 1, 1, 1, 1, 2, 2};
    const float WY0[8] = {.5625f, .6875f, .8125f, .9375f, .0625f, .1875f, .3125f, .4375f};
    const int   RY0[8] = {0, 0, 0, 0, 1, 1, 1, 1};
    const float WX2[8] = {.75f, .25f, .75f, .25f, .75f, .25f, .75f, .25f};
    const int   OX2[8] = {0, 1, 1, 2, 2, 3, 3, 4};
    const float WX1[8] = {.625f, .875f, .125f, .375f, .625f, .875f, .125f, .375f};
    const int   OX1[8] = {0, 0, 1, 1, 1, 1, 2, 2};
    const float WX0[8] = {.5625f, .6875f, .8125f, .9375f, .0625f, .1875f, .3125f, .4375f};
    const int   OX0[8] = {0, 0, 0, 0, 1, 1, 1, 1};

    const int ry2 = RY2[r]; const float wy2 = WY2[r];
    const int ry1 = RY1[r]; const float wy1 = WY1[r];
    const int ry0 = RY0[r]; const float wy0 = WY0[r];
    const int b2 = oxb >> 1, b1 = oxb >> 2, b0 = oxb >> 3;

    unsigned nibLo = 0, nibHi = 0;
    if (pi < 17) {
#pragma unroll
      for (int a = 0; a < 4; a++) {
        int p = 4 * pi + a;
        float v[8];
#pragma unroll
        for (int h = 0; h < 4; h++) {
          float2 t = unpack2(acc[a][h]);
          v[2 * h] = t.x; v[2 * h + 1] = t.y;
        }
        if (p < NP) {
          // L2: y-lerp 6 consecutive taps (vector loads)
          float ty2[6];
          {
            const float* rA = &sO2[p * 72 + ry2 * 12 + b2];
            const float* rB = rA + 12;
            float4 a4 = *(const float4*)rA;  float2 a2 = *(const float2*)(rA + 4);
            float4 b4 = *(const float4*)rB;  float2 b2v = *(const float2*)(rB + 4);
            ty2[0] = a4.x + wy2 * (b4.x - a4.x);
            ty2[1] = a4.y + wy2 * (b4.y - a4.y);
            ty2[2] = a4.z + wy2 * (b4.z - a4.z);
            ty2[3] = a4.w + wy2 * (b4.w - a4.w);
            ty2[4] = a2.x + wy2 * (b2v.x - a2.x);
            ty2[5] = a2.y + wy2 * (b2v.y - a2.y);
          }
          // L1: 4 taps
          float ty1[4];
          {
            const float* rA = &sO1[p * 32 + ry1 * 8 + b1];
            const float* rB = rA + 8;
            float2 a0 = *(const float2*)rA, a1 = *(const float2*)(rA + 2);
            float2 c0v = *(const float2*)rB, c1 = *(const float2*)(rB + 2);
            ty1[0] = a0.x + wy1 * (c0v.x - a0.x);
            ty1[1] = a0.y + wy1 * (c0v.y - a0.y);
            ty1[2] = a1.x + wy1 * (c1.x - a1.x);
            ty1[3] = a1.y + wy1 * (c1.y - a1.y);
          }
          // L0: 3 taps (row float4 + select by b0)
          float ty0[3];
          {
            const float* rA = &sO0[p * 12 + (ry0 << 2)];
            float4 a4 = *(const float4*)rA;
            float4 b4 = *(const float4*)(rA + 4);
            float a0 = b0 ? a4.y : a4.x, a1 = b0 ? a4.z : a4.y, a2 = b0 ? a4.w : a4.z;
            float c0v = b0 ? b4.y : b4.x, c1 = b0 ? b4.z : b4.y, c2 = b0 ? b4.w : b4.z;
            ty0[0] = a0 + wy0 * (c0v - a0);
            ty0[1] = a1 + wy0 * (c1 - a1);
            ty0[2] = a2 + wy0 * (c2 - a2);
          }
#pragma unroll
          for (int q = 0; q < 8; q++) {
            float lo2 = ty2[OX2[q]], hi2 = ty2[OX2[q] + 1];
            float lo1 = ty1[OX1[q]], hi1 = ty1[OX1[q] + 1];
            float lo0 = ty0[OX0[q]], hi0 = ty0[OX0[q] + 1];
            v[q] += lo2 + WX2[q] * (hi2 - lo2);
            v[q] += lo1 + WX1[q] * (hi1 - lo1);
            v[q] += lo0 + WX0[q] * (hi0 - lo0);
          }
        }
#pragma unroll
        for (int q = 0; q < 8; q++) {
          unsigned bit = (v[q] > 0.0f) ? 1u : 0u;
          if (q < 4) nibLo |= bit << ((q << 3) + a);
          else       nibHi |= bit << (((q - 4) << 3) + a);
        }
      }
      sSigns[pi * 32 + 2 * pj]     = nibLo;
      sSigns[pi * 32 + 2 * pj + 1] = nibHi;
    }
  }
  __syncthreads();

  // ---- vote via popcount masks, direct coalesced store ----
  if (tid < 128) {
    const unsigned char* sb8 = (const unsigned char*)sSigns;
    unsigned sw0 = 0, sw1 = 0;
#pragma unroll
    for (int g = 0; g < 8; g++) sw0 |= (unsigned)sb8[g * 128 + tid] << (4 * g);
#pragma unroll
    for (int g = 8; g < 16; g++) sw1 |= (unsigned)sb8[g * 128 + tid] << (4 * (g - 8));
    unsigned sw2 = sb8[16 * 128 + tid];
    int row = tid >> 4, col = tid & 15;
    float* op = out + (size_t)n * 12 * 65536 + (y0 + row) * 256 + (x0 + col);
#pragma unroll
    for (int k = 0; k < 12; k++) {
      int4 A = *(const int4*)&sMask[k][0];
      int4 B = *(const int4*)&sMask[k][4];
      int cnt = __popc(sw0 & (unsigned)A.x) + __popc(sw1 & (unsigned)A.y) +
                __popc(sw2 & (unsigned)A.z) - __popc(sw0 & (unsigned)A.w) -
                __popc(sw1 & (unsigned)B.x) - __popc(sw2 & (unsigned)B.y) + k;
      op[(size_t)k << 16] = (float)cnt;
    }
  }
}

// ---------------- launcher ----------------
extern "C" void kernel_launch(void* const* d_in, const int* in_sizes, int n_in,
                              void* d_out, int out_size) {
  const float* st[4] = {0, 0, 0, 0};
  const float* w[4] = {0, 0, 0, 0};
  const float* bb[4] = {0, 0, 0, 0};
  int bc = 0;
  for (int i = 0; i < n_in; i++) {
    switch (in_sizes[i]) {
      case 4194304:  st[0] = (const float*)d_in[i]; break;  // 8*512*32*32
      case 8388608:  st[1] = (const float*)d_in[i]; break;  // 8*256*64*64
      case 16777216: st[2] = (const float*)d_in[i]; break;  // 8*128*128*128
      case 33554432: st[3] = (const float*)d_in[i]; break;  // 8*64*256*256
      case 33792: w[0] = (const float*)d_in[i]; break;      // 66*512
      case 16896: w[1] = (const float*)d_in[i]; break;      // 66*256
      case 8448:  w[2] = (const float*)d_in[i]; break;      // 66*128
      case 4224:  w[3] = (const float*)d_in[i]; break;      // 66*64
      case 66:
        if (bc < 4) bb[bc++] = (const float*)d_in[i];       // b0..b3 in order
        break;
      default: break;  // last_only (==1 always per setup_inputs)
    }
  }

  conv_all<<<1344, 288>>>(st[0], st[1], st[2], w[0], w[1], w[2],
                          bb[0], bb[1], bb[2]);
  fused_kernel<<<dim3(512, 8), 288>>>(st[3], w[3], bb[3], (float*)d_out);
}

// round 7
// speedup vs baseline: 1.4131x; 1.0712x over previous
#include <cuda_runtime.h>

#define NP  66
#define NPP 72

// ---------------- scratch (no allocations allowed) ----------------
__device__ __align__(16) float g_O0[8 * NP * 32 * 32];
__device__ __align__(16) float g_O1[8 * NP * 64 * 64];
__device__ __align__(16) float g_O2[8 * NP * 128 * 128];

__constant__ int c_I[NP] = {
  0,0,0,0,0,0,0,0,0,0,0,
  1,1,1,1,1,1,1,1,1,1,
  2,2,2,2,2,2,2,2,2,
  3,3,3,3,3,3,3,3,
  4,4,4,4,4,4,4,
  5,5,5,5,5,5,
  6,6,6,6,6,
  7,7,7,7,
  8,8,8,
  9,9,
  10};
__constant__ int c_J[NP] = {
  1,2,3,4,5,6,7,8,9,10,11,
  2,3,4,5,6,7,8,9,10,11,
  3,4,5,6,7,8,9,10,11,
  4,5,6,7,8,9,10,11,
  5,6,7,8,9,10,11,
  6,7,8,9,10,11,
  7,8,9,10,11,
  8,9,10,11,
  9,10,11,
  10,11,
  11};

// ---------------- helpers ----------------
__device__ __forceinline__ void ffma2(unsigned long long& d,
                                      unsigned long long a,
                                      unsigned long long b) {
  asm("fma.rn.f32x2 %0, %1, %2, %0;" : "+l"(d) : "l"(a), "l"(b));
}
__device__ __forceinline__ unsigned long long pack2(float x) {
  unsigned long long r;
  asm("mov.b64 %0, {%1, %1};" : "=l"(r) : "f"(x));
  return r;
}
__device__ __forceinline__ float2 unpack2(unsigned long long u) {
  float2 r;
  asm("mov.b64 {%0, %1}, %2;" : "=f"(r.x), "=f"(r.y) : "l"(u));
  return r;
}
__device__ __forceinline__ unsigned su32(const void* p) {
  return (unsigned)__cvta_generic_to_shared(p);
}
__device__ __forceinline__ void cpa16(unsigned dst, const void* src) {
  asm volatile("cp.async.cg.shared.global [%0], [%1], 16;" :: "r"(dst), "l"(src));
}
__device__ __forceinline__ void cpa4(unsigned dst, const void* src) {
  asm volatile("cp.async.ca.shared.global [%0], [%1], 4;" :: "r"(dst), "l"(src));
}
#define CPA_COMMIT() asm volatile("cp.async.commit_group;" ::: "memory")
#define CPA_WAIT(n)  asm volatile("cp.async.wait_group %0;" :: "n"(n) : "memory")

// XOR swizzle on 16-byte-unit index (kills 2-way conflict of stride-32B LDS.128)
#define XSW(u) ((u) ^ (((u) >> 3) & 1))

#define XBUF (8 * 128)
#define WBUF (8 * NPP)

// compute one 8-channel chunk from buffer base pointers
#define COMPUTE8(Wb, Xb)                                                       \
  _Pragma("unroll")                                                            \
  for (int k = 0; k < 8; k++) {                                                \
    const float4 wv4 = *(const float4*)&(Wb)[k * NPP + 4 * pi];                \
    const ulonglong2 xA = *(const ulonglong2*)&(Xb)[k * 128 + xsA];            \
    const ulonglong2 xB = *(const ulonglong2*)&(Xb)[k * 128 + xsB];            \
    unsigned long long w_[4] = {pack2(wv4.x), pack2(wv4.y), pack2(wv4.z),      \
                                pack2(wv4.w)};                                 \
    unsigned long long x_[4] = {xA.x, xA.y, xB.x, xB.y};                       \
    _Pragma("unroll")                                                          \
    for (int a = 0; a < 4; a++)                                                \
      _Pragma("unroll")                                                        \
      for (int h = 0; h < 4; h++) ffma2(acc[a][h], w_[a], x_[h]);              \
  }

// issue loads of channel-chunk j into ring buffer j&3
#define ISSUE_CHUNK(j, XSTRIDE, CW)                                            \
  do {                                                                         \
    int _b = (j) & 3, _c0 = (j) * 8;                                           \
    if (hasx) cpa16(xd0 + _b * (XBUF * 4), xsrc + (size_t)_c0 * (XSTRIDE));    \
    cpa4(wda0 + _b * (WBUF * 4), wsa + _c0);                                   \
    if (hasb) cpa4(wdb0 + _b * (WBUF * 4), wsb + _c0);                         \
  } while (0)

// ---------------- conv body: 66 pairs x 128 px, 4-deep cp.async ring ---------
// block = 288 threads: pi=tid>>4 (pair group of 4), pj=tid&15 (8 px each)
// Ws: [4][8*NPP], Xs: [4][8*128]
template <int C, int SS>
__device__ __forceinline__ void conv_body(const float* __restrict__ X,
                                          const float* __restrict__ W,
                                          const float* __restrict__ bias,
                                          float* __restrict__ Og,
                                          int n, int px0,
                                          float* Ws, float* Xs) {
  const int tid = threadIdx.x;
  const int pi = tid >> 4, pj = tid & 15;
  const int xsA = 4 * XSW(2 * pj), xsB = 4 * XSW(2 * pj + 1);

  unsigned long long acc[4][4];
#pragma unroll
  for (int a = 0; a < 4; a++) {
    int p = 4 * pi + a;
    unsigned long long pk = pack2((p < NP) ? bias[p] : 0.0f);
#pragma unroll
    for (int h = 0; h < 4; h++) acc[a][h] = pk;
  }

  // X slots: one 16B per thread (tid<256): c=tid>>5, q=tid&31
  const bool hasx = tid < 256;
  const int c_ = tid >> 5, q_ = tid & 31;
  const unsigned xd0 = su32(&Xs[c_ * 128 + 4 * XSW(q_)]);
  const float* xsrc = X + (size_t)n * C * SS + px0 + (size_t)c_ * SS + 4 * q_;

  // W slots (transpose in flight): s = k*66+p, s in [0,528)
  const int ka = tid / 66, pa = tid - 66 * ka;
  const int sb_ = tid + 288;
  const bool hasb = sb_ < 528;
  const int kb = sb_ / 66, pb = sb_ - 66 * kb;
  const unsigned wda0 = su32(&Ws[ka * NPP + pa]);
  const unsigned wdb0 = su32(&Ws[kb * NPP + pb]);
  const float* wsa = W + pa * C + ka;
  const float* wsb = W + pb * C + kb;

  // zero the pad slots (p in 66..71) of all 4 buffers, once
  if (tid < 192) {
    int b = tid / 48, r = tid - 48 * b;
    int k = r / 6, p = 66 + (r - 6 * k);
    Ws[b * WBUF + k * NPP + p] = 0.0f;
  }

  // preload chunks 0..2 (three groups)
  ISSUE_CHUNK(0, SS, C); CPA_COMMIT();
  ISSUE_CHUNK(1, SS, C); CPA_COMMIT();
  ISSUE_CHUNK(2, SS, C); CPA_COMMIT();

  const int NIT = C / 8;
  for (int i = 0; i < NIT; i++) {
    CPA_WAIT(2);          // chunk i resident
    __syncthreads();      // also guards ring-buffer reuse
    {
      const float* Wb = Ws + (i & 3) * WBUF;
      const float* Xb = Xs + (i & 3) * XBUF;
      COMPUTE8(Wb, Xb);
    }
    if (i + 3 < NIT) ISSUE_CHUNK(i + 3, SS, C);
    CPA_COMMIT();         // uniform group count (empty on tail)
  }

  float* On = Og + (size_t)n * NP * SS + px0 + 8 * pj;
#pragma unroll
  for (int a = 0; a < 4; a++) {
    int p = 4 * pi + a;
    if (p < NP) {
      ulonglong2 v0, v1;
      v0.x = acc[a][0]; v0.y = acc[a][1];
      v1.x = acc[a][2]; v1.y = acc[a][3];
      *(ulonglong2*)&On[(size_t)p * SS] = v0;
      *(ulonglong2*)&On[(size_t)p * SS + 4] = v1;
    }
  }
}

// ---------------- merged conv for stages 0..2 ----------------
__global__ __launch_bounds__(288, 3) void conv_all(
    const float* __restrict__ s0, const float* __restrict__ s1,
    const float* __restrict__ s2, const float* __restrict__ w0,
    const float* __restrict__ w1, const float* __restrict__ w2,
    const float* __restrict__ b0, const float* __restrict__ b1,
    const float* __restrict__ b2) {
  __shared__ __align__(16) float Ws[4 * WBUF];
  __shared__ __align__(16) float Xs[4 * XBUF];
  int bid = blockIdx.x;
  if (bid < 64) {
    conv_body<512, 32 * 32>(s0, w0, b0, g_O0, bid >> 3, (bid & 7) << 7, Ws, Xs);
  } else if (bid < 320) {
    int q = bid - 64;
    conv_body<256, 64 * 64>(s1, w1, b1, g_O1, q >> 5, (q & 31) << 7, Ws, Xs);
  } else {
    int q = bid - 320;
    conv_body<128, 128 * 128>(s2, w2, b2, g_O2, q >> 7, (q & 127) << 7, Ws, Xs);
  }
}

// ---------------- fused: stage3 conv + bilinear pyramid sum + popc vote ------
// tile = 8 rows x 16 cols, flat px = row*16+col; thread pj owns px 8pj..8pj+7
__global__ __launch_bounds__(288, 2) void fused_kernel(
    const float* __restrict__ X, const float* __restrict__ W,
    const float* __restrict__ bias, float* __restrict__ out) {
  __shared__ __align__(16) float Ws[4 * WBUF];
  __shared__ __align__(16) float Xs[4 * XBUF];
  __shared__ __align__(16) float sO2[NP * 72];   // 6 rows x 10 cols (pad 12)
  __shared__ __align__(16) float sO1[NP * 32];   // 4 x 6 (pad 8)
  __shared__ __align__(16) float sO0[NP * 12];   // 3 x 4
  __shared__ unsigned sSigns[17 * 32];           // [pi][128 px] nibble bytes
  __shared__ __align__(16) int sMask[12][8];

  const int tid = threadIdx.x;
  const int pi = tid >> 4, pj = tid & 15;
  const int xsA = 4 * XSW(2 * pj), xsB = 4 * XSW(2 * pj + 1);
  const int n = blockIdx.y;
  const int ty = blockIdx.x >> 4, tx = blockIdx.x & 15;
  const int y0 = ty << 3, x0 = tx << 4;

  // ---- mainloop slot addressing ----
  const bool hasx = tid < 256;
  const int c_ = tid >> 5, q_ = tid & 31;
  const unsigned xd0 = su32(&Xs[c_ * 128 + 4 * XSW(q_)]);
  const float* Xn = X + (size_t)n * 64 * 65536;
  const float* xsrc = Xn + (size_t)c_ * 65536 + (y0 + (q_ >> 2)) * 256 + x0 + ((q_ & 3) << 2);
  const int ka = tid / 66, pa = tid - 66 * ka;
  const int sb_ = tid + 288;
  const bool hasb = sb_ < 528;
  const int kb = sb_ / 66, pb = sb_ - 66 * kb;
  const unsigned wda0 = su32(&Ws[ka * NPP + pa]);
  const unsigned wdb0 = su32(&Ws[kb * NPP + pb]);
  const float* wsa = W + pa * 64 + ka;
  const float* wsb = W + pb * 64 + kb;

  // preload chunks 0..2 (groups 0..2)
  ISSUE_CHUNK(0, 65536, 64); CPA_COMMIT();
  ISSUE_CHUNK(1, 65536, 64); CPA_COMMIT();
  ISSUE_CHUNK(2, 65536, 64); CPA_COMMIT();

  // ---- sO staging via fire-and-forget cp.async (group 3) ----
  {  // O2 region (128x128 src): 6 rows x 10 cols per pair, pad 12
    const float* src = g_O2 + (size_t)n * NP * 16384;
    int by = (y0 >> 1) - 1, bx = (x0 >> 1) - 1;
    for (int i = tid; i < NP * 60; i += 288) {
      int p = i / 60, cell = i - p * 60;
      int rr = cell / 10, cc = cell - rr * 10;
      int sy = min(max(by + rr, 0), 127);
      int sx = min(max(bx + cc, 0), 127);
      cpa4(su32(&sO2[p * 72 + rr * 12 + cc]), &src[p * 16384 + sy * 128 + sx]);
    }
  }
  {  // O1 region (64x64 src): 4 x 6, pad 8
    const float* src = g_O1 + (size_t)n * NP * 4096;
    int by = (y0 >> 2) - 1, bx = (x0 >> 2) - 1;
    for (int i = tid; i < NP * 24; i += 288) {
      int p = i / 24, cell = i - p * 24;
      int rr = cell / 6, cc = cell - rr * 6;
      int sy = min(max(by + rr, 0), 63);
      int sx = min(max(bx + cc, 0), 63);
      cpa4(su32(&sO1[p * 32 + rr * 8 + cc]), &src[p * 4096 + sy * 64 + sx]);
    }
  }
  {  // O0 region (32x32 src): 3 x 4
    const float* src = g_O0 + (size_t)n * NP * 1024;
    int by = (y0 >> 3) - 1, bx = (x0 >> 3) - 1;
    for (int i = tid; i < NP * 12; i += 288) {
      int p = i / 12, cell = i - p * 12;
      int rr = cell >> 2, cc = cell & 3;
      int sy = min(max(by + rr, 0), 31);
      int sx = min(max(bx + cc, 0), 31);
      cpa4(su32(&sO0[p * 12 + rr * 4 + cc]), &src[p * 1024 + sy * 32 + sx]);
    }
  }
  CPA_COMMIT();   // group 3 = staging

  // vote masks (static function of c_I/c_J)
  if (tid >= 200 && tid < 212) {
    int k = tid - 200;
    int m[6] = {0, 0, 0, 0, 0, 0};
    for (int p = 0; p < NP; p++) {
      int word = p >> 5, bit = p & 31;
      if (c_I[p] == k) m[word] |= 1 << bit;
      if (c_J[p] == k) m[3 + word] |= 1 << bit;
    }
#pragma unroll
    for (int t = 0; t < 6; t++) sMask[k][t] = m[t];
    sMask[k][6] = k; sMask[k][7] = 0;
  }
  // zero the weight pad slots of all 4 buffers
  if (tid < 192) {
    int b = tid / 48, r = tid - 48 * b;
    int k = r / 6, p = 66 + (r - 6 * k);
    Ws[b * WBUF + k * NPP + p] = 0.0f;
  }

  // ---- stage3 GEMM mainloop (C=64), 4-deep cp.async ring ----
  unsigned long long acc[4][4];
#pragma unroll
  for (int a = 0; a < 4; a++) {
    int p = 4 * pi + a;
    unsigned long long pk = pack2((p < NP) ? bias[p] : 0.0f);
#pragma unroll
    for (int h = 0; h < 4; h++) acc[a][h] = pk;
  }

  // commit order: G0=c0, G1=c1, G2=c2, G3=stage, then one group per iter.
  // wait(2) at iter i leaves the 2 newest groups pending -> chunk i resident;
  // staging (G3) complete by iter 2 < epilogue.
  for (int i = 0; i < 8; i++) {
    CPA_WAIT(2);
    __syncthreads();
    {
      const float* Wb = Ws + (i & 3) * WBUF;
      const float* Xb = Xs + (i & 3) * XBUF;
      COMPUTE8(Wb, Xb);
    }
    if (i + 3 < 8) ISSUE_CHUNK(i + 3, 65536, 64);
    CPA_COMMIT();
  }
  __syncthreads();  // sSigns/sO consumed below; ensure all compute done

  // ---- epilogue: separable bilinear (octet-shared taps) + sign nibbles ----
  {
    const int r = pj >> 1;          // output row in tile (0..7)
    const int oxb = (pj & 1) << 3;  // column octet base (0 or 8)
    const float WY2[8] = {.75f, .25f, .75f, .25f, .75f, .25f, .75f, .25f};
    const int   RY2[8] = {0, 1, 1, 2, 2, 3, 3, 4};
    const float WY1[8] = {.625f, .875f, .125f, .375f, .625f, .875f, .125f, .375f};
    const int   RY1[8] = {0, 0, 1, 1, 1, 1, 2, 2};
    const float WY0[8] = {.5625f, .6875f, .8125f, .9375f, .0625f, .1875f, .3125f, .4375f};
    const int   RY0[8] = {0, 0, 0, 0, 1, 1, 1, 1};
    const float WX2[8] = {.75f, .25f, .75f, .25f, .75f, .25f, .75f, .25f};
    const int   OX2[8] = {0, 1, 1, 2, 2, 3, 3, 4};
    const float WX1[8] = {.625f, .875f, .125f, .375f, .625f, .875f, .125f, .375f};
    const int   OX1[8] = {0, 0, 1, 1, 1, 1, 2, 2};
    const float WX0[8] = {.5625f, .6875f, .8125f, .9375f, .0625f, .1875f, .3125f, .4375f};
    const int   OX0[8] = {0, 0, 0, 0, 1, 1, 1, 1};

    const int ry2 = RY2[r]; const float wy2 = WY2[r];
    const int ry1 = RY1[r]; const float wy1 = WY1[r];
    const int ry0 = RY0[r]; const float wy0 = WY0[r];
    const int b2 = oxb >> 1, b1 = oxb >> 2, b0 = oxb >> 3;

    unsigned nibLo = 0, nibHi = 0;
    if (pi < 17) {
#pragma unroll
      for (int a = 0; a < 4; a++) {
        int p = 4 * pi + a;
        float v[8];
#pragma unroll
        for (int h = 0; h < 4; h++) {
          float2 t = unpack2(acc[a][h]);
          v[2 * h] = t.x; v[2 * h + 1] = t.y;
        }
        if (p < NP) {
          // L2: y-lerp 6 consecutive taps (vector loads)
          float ty2[6];
          {
            const float* rA = &sO2[p * 72 + ry2 * 12 + b2];
            const float* rB = rA + 12;
            float4 a4 = *(const float4*)rA;  float2 a2 = *(const float2*)(rA + 4);
            float4 b4 = *(const float4*)rB;  float2 b2v = *(const float2*)(rB + 4);
            ty2[0] = a4.x + wy2 * (b4.x - a4.x);
            ty2[1] = a4.y + wy2 * (b4.y - a4.y);
            ty2[2] = a4.z + wy2 * (b4.z - a4.z);
            ty2[3] = a4.w + wy2 * (b4.w - a4.w);
            ty2[4] = a2.x + wy2 * (b2v.x - a2.x);
            ty2[5] = a2.y + wy2 * (b2v.y - a2.y);
          }
          // L1: 4 taps
          float ty1[4];
          {
            const float* rA = &sO1[p * 32 + ry1 * 8 + b1];
            const float* rB = rA + 8;
            float2 a0 = *(const float2*)rA, a1 = *(const float2*)(rA + 2);
            float2 c0v = *(const float2*)rB, c1 = *(const float2*)(rB + 2);
            ty1[0] = a0.x + wy1 * (c0v.x - a0.x);
            ty1[1] = a0.y + wy1 * (c0v.y - a0.y);
            ty1[2] = a1.x + wy1 * (c1.x - a1.x);
            ty1[3] = a1.y + wy1 * (c1.y - a1.y);
          }
          // L0: 3 taps (row float4 + select by b0)
          float ty0[3];
          {
            const float* rA = &sO0[p * 12 + (ry0 << 2)];
            float4 a4 = *(const float4*)rA;
            float4 b4 = *(const float4*)(rA + 4);
            float a0 = b0 ? a4.y : a4.x, a1 = b0 ? a4.z : a4.y, a2 = b0 ? a4.w : a4.z;
            float c0v = b0 ? b4.y : b4.x, c1 = b0 ? b4.z : b4.y, c2 = b0 ? b4.w : b4.z;
            ty0[0] = a0 + wy0 * (c0v - a0);
            ty0[1] = a1 + wy0 * (c1 - a1);
            ty0[2] = a2 + wy0 * (c2 - a2);
          }
#pragma unroll
          for (int q = 0; q < 8; q++) {
            float lo2 = ty2[OX2[q]], hi2 = ty2[OX2[q] + 1];
            float lo1 = ty1[OX1[q]], hi1 = ty1[OX1[q] + 1];
            float lo0 = ty0[OX0[q]], hi0 = ty0[OX0[q] + 1];
            v[q] += lo2 + WX2[q] * (hi2 - lo2);
            v[q] += lo1 + WX1[q] * (hi1 - lo1);
            v[q] += lo0 + WX0[q] * (hi0 - lo0);
          }
        }
#pragma unroll
        for (int q = 0; q < 8; q++) {
          unsigned bit = (v[q] > 0.0f) ? 1u : 0u;
          if (q < 4) nibLo |= bit << ((q << 3) + a);
          else       nibHi |= bit << (((q - 4) << 3) + a);
        }
      }
      sSigns[pi * 32 + 2 * pj]     = nibLo;
      sSigns[pi * 32 + 2 * pj + 1] = nibHi;
    }
  }
  __syncthreads();

  // ---- vote via popcount masks, direct coalesced store ----
  if (tid < 128) {
    const unsigned char* sb8 = (const unsigned char*)sSigns;
    unsigned sw0 = 0, sw1 = 0;
#pragma unroll
    for (int g = 0; g < 8; g++) sw0 |= (unsigned)sb8[g * 128 + tid] << (4 * g);
#pragma unroll
    for (int g = 8; g < 16; g++) sw1 |= (unsigned)sb8[g * 128 + tid] << (4 * (g - 8));
    unsigned sw2 = sb8[16 * 128 + tid];
    int row = tid >> 4, col = tid & 15;
    float* op = out + (size_t)n * 12 * 65536 + (y0 + row) * 256 + (x0 + col);
#pragma unroll
    for (int k = 0; k < 12; k++) {
      int4 A = *(const int4*)&sMask[k][0];
      int4 B = *(const int4*)&sMask[k][4];
      int cnt = __popc(sw0 & (unsigned)A.x) + __popc(sw1 & (unsigned)A.y) +
                __popc(sw2 & (unsigned)A.z) - __popc(sw0 & (unsigned)A.w) -
                __popc(sw1 & (unsigned)B.x) - __popc(sw2 & (unsigned)B.y) + k;
      op[(size_t)k << 16] = (float)cnt;
    }
  }
}

// ---------------- launcher ----------------
extern "C" void kernel_launch(void* const* d_in, const int* in_sizes, int n_in,
                              void* d_out, int out_size) {
  const float* st[4] = {0, 0, 0, 0};
  const float* w[4] = {0, 0, 0, 0};
  const float* bb[4] = {0, 0, 0, 0};
  int bc = 0;
  for (int i = 0; i < n_in; i++) {
    switch (in_sizes[i]) {
      case 4194304:  st[0] = (const float*)d_in[i]; break;  // 8*512*32*32
      case 8388608:  st[1] = (const float*)d_in[i]; break;  // 8*256*64*64
      case 16777216: st[2] = (const float*)d_in[i]; break;  // 8*128*128*128
      case 33554432: st[3] = (const float*)d_in[i]; break;  // 8*64*256*256
      case 33792: w[0] = (const float*)d_in[i]; break;      // 66*512
      case 16896: w[1] = (const float*)d_in[i]; break;      // 66*256
      case 8448:  w[2] = (const float*)d_in[i]; break;      // 66*128
      case 4224:  w[3] = (const float*)d_in[i]; break;      // 66*64
      case 66:
        if (bc < 4) bb[bc++] = (const float*)d_in[i];       // b0..b3 in order
        break;
      default: break;  // last_only (==1 always per setup_inputs)
    }
  }

  conv_all<<<1344, 288>>>(st[0], st[1], st[2], w[0], w[1], w[2],
                          bb[0], bb[1], bb[2]);
  fused_kernel<<<dim3(512, 8), 288>>>(st[3], w[3], bb[3], (float*)d_out);
}

// round 8
// speedup vs baseline: 1.5425x; 1.0916x over previous
#include <cuda_runtime.h>

#define NP  66
#define NPP 72

// ---------------- scratch (no allocations allowed) ----------------
__device__ __align__(16) float g_O0[8 * NP * 32 * 32];
__device__ __align__(16) float g_O1[8 * NP * 64 * 64];
__device__ __align__(16) float g_O2[8 * NP * 128 * 128];

// Precomputed OvO vote masks over the 66 pairs (+6 pad bits always 0).
// c_MA[k] = {Imask word0, word1, word2, Jmask word0}
// c_MB[k] = {Jmask word1, word2, 0, 0}
__constant__ int4 c_MA[12] = {
  {0x000007FF, 0x00000000, 0x0, 0x00000000},
  {0x001FF800, 0x00000000, 0x0, 0x00000001},
  {0x3FE00000, 0x00000000, 0x0, 0x00000802},
  {(int)0xC0000000, 0x0000003F, 0x0, 0x00201004},
  {0x00000000, 0x00001FC0, 0x0, 0x40402008},
  {0x00000000, 0x0007E000, 0x0, (int)0x80804010},
  {0x00000000, 0x00F80000, 0x0, 0x01008020},
  {0x00000000, 0x0F000000, 0x0, 0x02010040},
  {0x00000000, 0x70000000, 0x0, 0x04020080},
  {0x00000000, (int)0x80000000, 0x1, 0x08040100},
  {0x00000000, 0x00000000, 0x2, 0x10080200},
  {0x00000000, 0x00000000, 0x0, 0x20100400}};
__constant__ int4 c_MB[12] = {
  {0x00000000, 0x0, 0, 0}, {0x00000000, 0x0, 0, 0},
  {0x00000000, 0x0, 0, 0}, {0x00000000, 0x0, 0, 0},
  {0x00000000, 0x0, 0, 0}, {0x00000040, 0x0, 0, 0},
  {0x00002081, 0x0, 0, 0}, {0x00084102, 0x0, 0, 0},
  {0x01108204, 0x0, 0, 0}, {0x12210408, 0x0, 0, 0},
  {(int)0xA4420810, 0x0, 0, 0}, {0x48841020, 0x3, 0, 0}};

// ---------------- helpers ----------------
__device__ __forceinline__ void ffma2(unsigned long long& d,
                                      unsigned long long a,
                                      unsigned long long b) {
  asm("fma.rn.f32x2 %0, %1, %2, %0;" : "+l"(d) : "l"(a), "l"(b));
}
__device__ __forceinline__ unsigned long long pack2(float x) {
  unsigned long long r;
  asm("mov.b64 %0, {%1, %1};" : "=l"(r) : "f"(x));
  return r;
}
__device__ __forceinline__ float2 unpack2(unsigned long long u) {
  float2 r;
  asm("mov.b64 {%0, %1}, %2;" : "=f"(r.x), "=f"(r.y) : "l"(u));
  return r;
}
__device__ __forceinline__ unsigned su32(const void* p) {
  return (unsigned)__cvta_generic_to_shared(p);
}
__device__ __forceinline__ void cpa16(unsigned dst, const void* src) {
  asm volatile("cp.async.cg.shared.global [%0], [%1], 16;" :: "r"(dst), "l"(src));
}
__device__ __forceinline__ void cpa4(unsigned dst, const void* src) {
  asm volatile("cp.async.ca.shared.global [%0], [%1], 4;" :: "r"(dst), "l"(src));
}
#define CPA_COMMIT() asm volatile("cp.async.commit_group;" ::: "memory")
#define CPA_WAIT(n)  asm volatile("cp.async.wait_group %0;" :: "n"(n) : "memory")

#define XBUF (8 * 128)
#define WBUF (8 * NPP)

// compute one 8-channel chunk: warp 'wrp' owns pairs 8wrp..8wrp+7,
// lane 'ln' owns pixels 4ln..4ln+3
#define COMPUTE8(Wb, Xb)                                                       \
  _Pragma("unroll")                                                            \
  for (int k = 0; k < 8; k++) {                                                \
    const float4 wA = *(const float4*)&(Wb)[k * NPP + 8 * wrp];                \
    const float4 wB = *(const float4*)&(Wb)[k * NPP + 8 * wrp + 4];            \
    const ulonglong2 xv = *(const ulonglong2*)&(Xb)[k * 128 + 4 * ln];         \
    unsigned long long w_[8] = {pack2(wA.x), pack2(wA.y), pack2(wA.z),         \
                                pack2(wA.w), pack2(wB.x), pack2(wB.y),         \
                                pack2(wB.z), pack2(wB.w)};                     \
    _Pragma("unroll")                                                          \
    for (int a = 0; a < 8; a++) {                                              \
      ffma2(acc[a][0], w_[a], xv.x);                                           \
      ffma2(acc[a][1], w_[a], xv.y);                                           \
    }                                                                          \
  }

// issue loads of channel-chunk j into ring buffer j&3
#define ISSUE_CHUNK(j, XSTRIDE)                                                \
  do {                                                                         \
    int _b = (j) & 3, _c0 = (j) * 8;                                           \
    if (hasx) cpa16(xd0 + _b * (XBUF * 4), xsrc + (size_t)_c0 * (XSTRIDE));    \
    cpa4(wda0 + _b * (WBUF * 4), wsa + _c0);                                   \
    if (hasb) cpa4(wdb0 + _b * (WBUF * 4), wsb + _c0);                         \
  } while (0)

// ---------------- conv body: 66 pairs x 128 px, 4-deep cp.async ring ---------
template <int C, int SS>
__device__ __forceinline__ void conv_body(const float* __restrict__ X,
                                          const float* __restrict__ W,
                                          const float* __restrict__ bias,
                                          float* __restrict__ Og,
                                          int n, int px0,
                                          float* Ws, float* Xs) {
  const int tid = threadIdx.x;
  const int wrp = tid >> 5, ln = tid & 31;

  unsigned long long acc[8][2];
#pragma unroll
  for (int a = 0; a < 8; a++) {
    int p = 8 * wrp + a;
    unsigned long long pk = pack2((p < NP) ? bias[p] : 0.0f);
    acc[a][0] = pk; acc[a][1] = pk;
  }

  // X slots: one 16B per thread (tid<256): ch=tid>>5, t=tid&31
  const bool hasx = tid < 256;
  const int ch_ = tid >> 5, t_ = tid & 31;
  const unsigned xd0 = su32(&Xs[ch_ * 128 + 4 * t_]);
  const float* xsrc = X + (size_t)n * C * SS + px0 + (size_t)ch_ * SS + 4 * t_;

  // W slots (transpose in flight): s = k*66+p, s in [0,528)
  const int ka = tid / 66, pa = tid - 66 * ka;
  const int sb_ = tid + 288;
  const bool hasb = sb_ < 528;
  const int kb = sb_ / 66, pb = sb_ - 66 * kb;
  const unsigned wda0 = su32(&Ws[ka * NPP + pa]);
  const unsigned wdb0 = su32(&Ws[kb * NPP + pb]);
  const float* wsa = W + pa * C + ka;
  const float* wsb = W + pb * C + kb;

  // zero the pad slots (p in 66..71) of all 4 buffers, once
  if (tid < 192) {
    int b = tid / 48, r = tid - 48 * b;
    int k = r / 6, p = 66 + (r - 6 * k);
    Ws[b * WBUF + k * NPP + p] = 0.0f;
  }

  ISSUE_CHUNK(0, SS); CPA_COMMIT();
  ISSUE_CHUNK(1, SS); CPA_COMMIT();
  ISSUE_CHUNK(2, SS); CPA_COMMIT();

  const int NIT = C / 8;
  for (int i = 0; i < NIT; i++) {
    CPA_WAIT(2);
    __syncthreads();
    {
      const float* Wb = Ws + (i & 3) * WBUF;
      const float* Xb = Xs + (i & 3) * XBUF;
      COMPUTE8(Wb, Xb);
    }
    if (i + 3 < NIT) ISSUE_CHUNK(i + 3, SS);
    CPA_COMMIT();
  }

  float* On = Og + (size_t)n * NP * SS + px0 + 4 * ln;
#pragma unroll
  for (int a = 0; a < 8; a++) {
    int p = 8 * wrp + a;
    if (p < NP) {
      ulonglong2 v;
      v.x = acc[a][0]; v.y = acc[a][1];
      *(ulonglong2*)&On[(size_t)p * SS] = v;
    }
  }
}

// ---------------- merged conv for stages 0..2 ----------------
__global__ __launch_bounds__(288, 3) void conv_all(
    const float* __restrict__ s0, const float* __restrict__ s1,
    const float* __restrict__ s2, const float* __restrict__ w0,
    const float* __restrict__ w1, const float* __restrict__ w2,
    const float* __restrict__ b0, const float* __restrict__ b1,
    const float* __restrict__ b2) {
  __shared__ __align__(16) float Ws[4 * WBUF];
  __shared__ __align__(16) float Xs[4 * XBUF];
  int bid = blockIdx.x;
  if (bid < 64) {
    conv_body<512, 32 * 32>(s0, w0, b0, g_O0, bid >> 3, (bid & 7) << 7, Ws, Xs);
  } else if (bid < 320) {
    int q = bid - 64;
    conv_body<256, 64 * 64>(s1, w1, b1, g_O1, q >> 5, (q & 31) << 7, Ws, Xs);
  } else {
    int q = bid - 320;
    conv_body<128, 128 * 128>(s2, w2, b2, g_O2, q >> 7, (q & 127) << 7, Ws, Xs);
  }
}

// ---------------- fused: stage3 conv + bilinear pyramid sum + popc vote ------
// tile = 8 rows x 16 cols; warp = 8 pairs, lane = 4-px quad (row=ln>>2, qc=ln&3)
__global__ __launch_bounds__(288, 2) void fused_kernel(
    const float* __restrict__ X, const float* __restrict__ W,
    const float* __restrict__ bias, float* __restrict__ out) {
  __shared__ __align__(16) float Ws[4 * WBUF];
  __shared__ __align__(16) float Xs[4 * XBUF];   // reused for sign bytes later
  __shared__ __align__(16) float sO2[NP * 96];   // 6 rows x 16 cols (xoff 3)
  __shared__ __align__(16) float sO1[NP * 48];   // 4 rows x 12 cols (xoff 3)
  __shared__ __align__(16) float sO0[NP * 24];   // 3 rows x 8 cols (xoff off0)

  const int tid = threadIdx.x;
  const int wrp = tid >> 5, ln = tid & 31;
  const int n = blockIdx.y;
  const int ty = blockIdx.x >> 4, tx = blockIdx.x & 15;
  const int y0 = ty << 3, x0 = tx << 4;

  // ---- mainloop slot addressing ----
  const bool hasx = tid < 256;
  const int ch_ = tid >> 5, t_ = tid & 31;
  const unsigned xd0 = su32(&Xs[ch_ * 128 + 4 * t_]);
  const float* Xn = X + (size_t)n * 64 * 65536;
  const float* xsrc = Xn + (size_t)ch_ * 65536 + (y0 + (t_ >> 2)) * 256 + x0 + ((t_ & 3) << 2);
  const int ka = tid / 66, pa = tid - 66 * ka;
  const int sb_ = tid + 288;
  const bool hasb = sb_ < 528;
  const int kb = sb_ / 66, pb = sb_ - 66 * kb;
  const unsigned wda0 = su32(&Ws[ka * NPP + pa]);
  const unsigned wdb0 = su32(&Ws[kb * NPP + pb]);
  const float* wsa = W + pa * 64 + ka;
  const float* wsb = W + pb * 64 + kb;

  ISSUE_CHUNK(0, 65536); CPA_COMMIT();
  ISSUE_CHUNK(1, 65536); CPA_COMMIT();
  ISSUE_CHUNK(2, 65536); CPA_COMMIT();

  // ---- sO staging (group 3): aligned-span layouts ----
  const int by2 = (y0 >> 1) - 1, a2 = 8 * tx - 4;
  const int by1 = (y0 >> 2) - 1, a1 = 4 * tx - 4;
  const int by0 = (y0 >> 3) - 1;
  const int bx0 = 2 * tx - 1, a0x = bx0 & ~3, off0 = bx0 & 3;
  const float* s2g = g_O2 + (size_t)n * NP * 16384;
  const float* s1g = g_O1 + (size_t)n * NP * 4096;
  const float* s0g = g_O0 + (size_t)n * NP * 1024;

  if (tx >= 1 && tx <= 14) {
    for (int i = tid; i < NP * 24; i += 288) {         // O2: 6 rows x 4 chunks
      int p = i / 24, r = i - p * 24;
      int rr = r >> 2, c4 = (r & 3) << 2;
      int sy = min(max(by2 + rr, 0), 127);
      cpa16(su32(&sO2[p * 96 + rr * 16 + c4]), s2g + p * 16384 + sy * 128 + a2 + c4);
    }
    for (int i = tid; i < NP * 12; i += 288) {         // O1: 4 rows x 3 chunks
      int p = i / 12, r = i - p * 12;
      int rr = r / 3, c4 = (r - rr * 3) << 2;
      int sy = min(max(by1 + rr, 0), 63);
      cpa16(su32(&sO1[p * 48 + rr * 12 + c4]), s1g + p * 4096 + sy * 64 + a1 + c4);
    }
    for (int i = tid; i < NP * 6; i += 288) {          // O0: 3 rows x 2 chunks
      int p = i / 6, r = i - p * 6;
      int rr = r >> 1, c4 = (r & 1) << 2;
      int sy = min(max(by0 + rr, 0), 31);
      cpa16(su32(&sO0[p * 24 + rr * 8 + c4]), s0g + p * 1024 + sy * 32 + a0x + c4);
    }
  } else {  // edge tiles: scalar clamped staging (same layouts)
    for (int i = tid; i < NP * 96; i += 288) {
      int p = i / 96, r = i - p * 96;
      int rr = r >> 4, c = r & 15;
      int sy = min(max(by2 + rr, 0), 127);
      int sx = min(max(a2 + c, 0), 127);
      cpa4(su32(&sO2[p * 96 + rr * 16 + c]), s2g + p * 16384 + sy * 128 + sx);
    }
    for (int i = tid; i < NP * 48; i += 288) {
      int p = i / 48, r = i - p * 48;
      int rr = r / 12, c = r - rr * 12;
      int sy = min(max(by1 + rr, 0), 63);
      int sx = min(max(a1 + c, 0), 63);
      cpa4(su32(&sO1[p * 48 + rr * 12 + c]), s1g + p * 4096 + sy * 64 + sx);
    }
    for (int i = tid; i < NP * 24; i += 288) {
      int p = i / 24, r = i - p * 24;
      int rr = r >> 3, c = r & 7;
      int sy = min(max(by0 + rr, 0), 31);
      int sx = min(max(a0x + c, 0), 31);
      cpa4(su32(&sO0[p * 24 + rr * 8 + c]), s0g + p * 1024 + sy * 32 + sx);
    }
  }
  CPA_COMMIT();   // group 3 = staging

  // zero the weight pad slots of all 4 buffers
  if (tid < 192) {
    int b = tid / 48, r = tid - 48 * b;
    int k = r / 6, p = 66 + (r - 6 * k);
    Ws[b * WBUF + k * NPP + p] = 0.0f;
  }

  // ---- stage3 GEMM mainloop (C=64), 4-deep cp.async ring ----
  unsigned long long acc[8][2];
#pragma unroll
  for (int a = 0; a < 8; a++) {
    int p = 8 * wrp + a;
    unsigned long long pk = pack2((p < NP) ? bias[p] : 0.0f);
    acc[a][0] = pk; acc[a][1] = pk;
  }

  for (int i = 0; i < 8; i++) {
    CPA_WAIT(2);
    __syncthreads();
    {
      const float* Wb = Ws + (i & 3) * WBUF;
      const float* Xb = Xs + (i & 3) * XBUF;
      COMPUTE8(Wb, Xb);
    }
    if (i + 3 < 8) ISSUE_CHUNK(i + 3, 65536);
    CPA_COMMIT();
  }
  __syncthreads();  // all compute done; Xs ring now dead -> reuse for signs

  // ---- epilogue: separable bilinear (quad-shared taps) + sign bytes ----
  {
    const int r = ln >> 2, qc = ln & 3;
    const float WY2[8] = {.75f, .25f, .75f, .25f, .75f, .25f, .75f, .25f};
    const int   RY2[8] = {0, 1, 1, 2, 2, 3, 3, 4};
    const float WY1[8] = {.625f, .875f, .125f, .375f, .625f, .875f, .125f, .375f};
    const int   RY1[8] = {0, 0, 1, 1, 1, 1, 2, 2};
    const float WY0[8] = {.5625f, .6875f, .8125f, .9375f, .0625f, .1875f, .3125f, .4375f};
    const int   RY0[8] = {0, 0, 0, 0, 1, 1, 1, 1};
    const int ry2 = RY2[r]; const float wy2 = WY2[r];
    const int ry1 = RY1[r]; const float wy1 = WY1[r];
    const int ry0 = RY0[r]; const float wy0 = WY0[r];
    const int w0qc = (qc + 1) >> 1;       // {0,1,1,2}
    const float fx0adj = (qc & 1) ? 0.5f : 0.0f;

    const int   LX2[4] = {0, 1, 1, 2};
    const float FX2[4] = {.75f, .25f, .75f, .25f};
    const int   LX1[4] = {0, 0, 1, 1};
    const float FX1[4] = {.625f, .875f, .125f, .375f};
    const float FX0[4] = {.5625f, .6875f, .8125f, .9375f};

    unsigned by[4] = {0, 0, 0, 0};
#pragma unroll
    for (int a = 0; a < 8; a++) {
      int p = 8 * wrp + a;
      float v[4];
      float2 u0 = unpack2(acc[a][0]), u1 = unpack2(acc[a][1]);
      v[0] = u0.x; v[1] = u0.y; v[2] = u1.x; v[3] = u1.y;
      if (p < NP) {
        const float* A2 = &sO2[p * 96 + ry2 * 16 + 3 + 2 * qc];
        const float* B2 = A2 + 16;
        float t2[4];
#pragma unroll
        for (int t = 0; t < 4; t++) t2[t] = A2[t] + wy2 * (B2[t] - A2[t]);
        const float* A1 = &sO1[p * 48 + ry1 * 12 + 3 + qc];
        const float* B1 = A1 + 12;
        float t1[3];
#pragma unroll
        for (int t = 0; t < 3; t++) t1[t] = A1[t] + wy1 * (B1[t] - A1[t]);
        const float* A0 = &sO0[p * 24 + ry0 * 8 + off0 + w0qc];
        const float* B0 = A0 + 8;
        float t0[2];
#pragma unroll
        for (int t = 0; t < 2; t++) t0[t] = A0[t] + wy0 * (B0[t] - A0[t]);
#pragma unroll
        for (int q = 0; q < 4; q++) {
          v[q] += t2[LX2[q]] + FX2[q] * (t2[LX2[q] + 1] - t2[LX2[q]]);
          v[q] += t1[LX1[q]] + FX1[q] * (t1[LX1[q] + 1] - t1[LX1[q]]);
          float f0 = FX0[q] - fx0adj;
          v[q] += t0[0] + f0 * (t0[1] - t0[0]);
        }
      }
#pragma unroll
      for (int q = 0; q < 4; q++) by[q] |= ((v[q] > 0.0f) ? 1u : 0u) << a;
    }
    unsigned* sS32 = (unsigned*)Xs;
    sS32[wrp * 32 + ln] = by[0] | (by[1] << 8) | (by[2] << 16) | (by[3] << 24);
  }
  __syncthreads();

  // ---- vote via popcount against constant masks, coalesced store ----
  if (tid < 128) {
    const unsigned char* sb8 = (const unsigned char*)Xs;
    unsigned b0 = sb8[tid],           b1 = sb8[128 + tid];
    unsigned b2 = sb8[256 + tid],     b3 = sb8[384 + tid];
    unsigned b4 = sb8[512 + tid],     b5 = sb8[640 + tid];
    unsigned b6 = sb8[768 + tid],     b7 = sb8[896 + tid];
    unsigned b8 = sb8[1024 + tid];
    unsigned sw0 = b0 | (b1 << 8) | (b2 << 16) | (b3 << 24);
    unsigned sw1 = b4 | (b5 << 8) | (b6 << 16) | (b7 << 24);
    unsigned sw2 = b8;
    int row = tid >> 4, col = tid & 15;
    float* op = out + (size_t)n * 12 * 65536 + (y0 + row) * 256 + (x0 + col);
#pragma unroll
    for (int k = 0; k < 12; k++) {
      int4 A = c_MA[k];
      int4 B = c_MB[k];
      int cnt = __popc(sw0 & (unsigned)A.x) + __popc(sw1 & (unsigned)A.y) +
                __popc(sw2 & (unsigned)A.z) - __popc(sw0 & (unsigned)A.w) -
                __popc(sw1 & (unsigned)B.x) - __popc(sw2 & (unsigned)B.y) + k;
      op[(size_t)k << 16] = (float)cnt;
    }
  }
}

// ---------------- launcher ----------------
extern "C" void kernel_launch(void* const* d_in, const int* in_sizes, int n_in,
                              void* d_out, int out_size) {
  const float* st[4] = {0, 0, 0, 0};
  const float* w[4] = {0, 0, 0, 0};
  const float* bb[4] = {0, 0, 0, 0};
  int bc = 0;
  for (int i = 0; i < n_in; i++) {
    switch (in_sizes[i]) {
      case 4194304:  st[0] = (const float*)d_in[i]; break;  // 8*512*32*32
      case 8388608:  st[1] = (const float*)d_in[i]; break;  // 8*256*64*64
      case 16777216: st[2] = (const float*)d_in[i]; break;  // 8*128*128*128
      case 33554432: st[3] = (const float*)d_in[i]; break;  // 8*64*256*256
      case 33792: w[0] = (const float*)d_in[i]; break;      // 66*512
      case 16896: w[1] = (const float*)d_in[i]; break;      // 66*256
      case 8448:  w[2] = (const float*)d_in[i]; break;      // 66*128
      case 4224:  w[3] = (const float*)d_in[i]; break;      // 66*64
      case 66:
        if (bc < 4) bb[bc++] = (const float*)d_in[i];       // b0..b3 in order
        break;
      default: break;  // last_only (==1 always per setup_inputs)
    }
  }

  conv_all<<<1344, 288>>>(st[0], st[1], st[2], w[0], w[1], w[2],
                          bb[0], bb[1], bb[2]);
  fused_kernel<<<dim3(512, 8), 288>>>(st[3], w[3], bb[3], (float*)d_out);
}